// round 11
// baseline (speedup 1.0000x reference)
#include <cuda_runtime.h>
#include <cuda_bf16.h>
#include <cstdint>

#define DEV_INLINE __device__ __forceinline__

// ------------------------------- f32x2 helpers (GEMM kernels) -------------
struct U64F2 { union { unsigned long long u; float2 f; }; };
DEV_INLINE U64F2 f2fma(U64F2 a, U64F2 b, U64F2 c) {
    U64F2 d;
    asm("fma.rn.f32x2 %0, %1, %2, %3;" : "=l"(d.u) : "l"(a.u), "l"(b.u), "l"(c.u));
    return d;
}
DEV_INLINE U64F2 pk2(float v) {
    U64F2 d;
    asm("mov.b64 %0, {%1, %1};" : "=l"(d.u) : "f"(v));
    return d;
}

// ------------------------------- mma.sync helpers -------------------------
DEV_INLINE void mma16816(float* c, const uint32_t* a, const uint32_t* b) {
    asm volatile(
        "mma.sync.aligned.m16n8k16.row.col.f32.bf16.bf16.f32 "
        "{%0,%1,%2,%3}, {%4,%5,%6,%7}, {%8,%9}, {%0,%1,%2,%3};"
        : "+f"(c[0]), "+f"(c[1]), "+f"(c[2]), "+f"(c[3])
        : "r"(a[0]), "r"(a[1]), "r"(a[2]), "r"(a[3]), "r"(b[0]), "r"(b[1]));
}
DEV_INLINE uint32_t packbf(float lo, float hi) {  // low half = lo
    uint32_t r;
    asm("cvt.rn.bf16x2.f32 %0, %1, %2;" : "=r"(r) : "f"(hi), "f"(lo));
    return r;
}
DEV_INLINE float bfround(float x) {
    return __bfloat162float(__float2bfloat16(x));
}
DEV_INLINE float bflo(uint32_t u) { return __uint_as_float(u << 16); }
DEV_INLINE float bfhi(uint32_t u) { return __uint_as_float(u & 0xFFFF0000u); }

// ------------------------------- problem constants ------------------------
constexpr int Bc = 2, Pc = 2048, Hc = 8, DFc = 32;
constexpr float QSCALE = 0.17677669529663687f;  // 1/sqrt(32)

__device__ __align__(16) __nv_bfloat16 g_qbf[Bc * 8 * Pc * 32];   // [b,h,p,d] scaled
__device__ __align__(16) __nv_bfloat16 g_kbf[Bc * 8 * Pc * 32];   // [b,h,q,d]
__device__ __align__(16) __nv_bfloat16 g_vthi[Bc * 8 * 32 * Pc];  // [b,h,d,q]
__device__ __align__(16) __nv_bfloat16 g_vtlo[Bc * 8 * 32 * Pc];
__device__ __align__(16) float g_ctxt[Bc * Pc * 256];
__device__ __align__(16) float g_oscr[2 * Bc * Pc * 256];         // [ks,b,p,256]
__device__ __align__(16) float2 g_mlscr[2 * Bc * 8 * Pc];         // [ks,b,g,p]

// ---------------------------------------------------------------------------
// GEMM: C = A[M,K] @ Bw[N,K]^T. EPI=1: per-head q/k bf16 + v hi/lo transpose.
// ---------------------------------------------------------------------------
template <int EPI>
__global__ __launch_bounds__(256) void gemm_nt(const float* __restrict__ A,
                                               const float* __restrict__ Bw,
                                               float* __restrict__ C,
                                               int M, int N, int K) {
    __shared__ __align__(16) float As[64][68];
    __shared__ __align__(16) float Bs[64][68];

    const int tid = threadIdx.x;
    const int tx = tid & 15, ty = tid >> 4;
    const int m0 = blockIdx.x << 6, n0 = blockIdx.y << 6;
    const int bn = tid & 63;
    const int bk = (tid >> 6) << 4;

    U64F2 acc[4][2];
#pragma unroll
    for (int i = 0; i < 4; i++) {
        acc[i][0].f = make_float2(0.f, 0.f);
        acc[i][1].f = make_float2(0.f, 0.f);
    }

    for (int kc = 0; kc < K; kc += 64) {
#pragma unroll
        for (int i = 0; i < 4; i++) {
            int v = tid + (i << 8);
            int r = v >> 4, k4 = v & 15;
            *(float4*)&As[r][k4 << 2] =
                *(const float4*)&A[(size_t)(m0 + r) * K + kc + (k4 << 2)];
        }
#pragma unroll
        for (int c4 = 0; c4 < 4; c4++) {
            float4 bv = *(const float4*)&Bw[(size_t)(n0 + bn) * K + kc + bk + (c4 << 2)];
            Bs[bk + (c4 << 2) + 0][bn] = bv.x;
            Bs[bk + (c4 << 2) + 1][bn] = bv.y;
            Bs[bk + (c4 << 2) + 2][bn] = bv.z;
            Bs[bk + (c4 << 2) + 3][bn] = bv.w;
        }
        __syncthreads();
#pragma unroll 8
        for (int kk = 0; kk < 64; kk++) {
            float4 b01 = *(const float4*)&Bs[kk][tx << 2];
            U64F2 b0, b1;
            b0.f = make_float2(b01.x, b01.y);
            b1.f = make_float2(b01.z, b01.w);
#pragma unroll
            for (int i = 0; i < 4; i++) {
                U64F2 a2 = pk2(As[(ty << 2) + i][kk]);
                acc[i][0] = f2fma(a2, b0, acc[i][0]);
                acc[i][1] = f2fma(a2, b1, acc[i][1]);
            }
        }
        __syncthreads();
    }

    if (EPI == 0) {
#pragma unroll
        for (int i = 0; i < 4; i++) {
            float4 vout;
            vout.x = acc[i][0].f.x; vout.y = acc[i][0].f.y;
            vout.z = acc[i][1].f.x; vout.w = acc[i][1].f.y;
            *(float4*)&C[(size_t)(m0 + (ty << 2) + i) * N + n0 + (tx << 2)] = vout;
        }
    } else {
#pragma unroll
        for (int i = 0; i < 4; i++) {
            float vals[4] = {acc[i][0].f.x, acc[i][0].f.y, acc[i][1].f.x, acc[i][1].f.y};
            int r = m0 + (ty << 2) + i;
            int bb = r >> 11, p = r & 2047;
#pragma unroll
            for (int j = 0; j < 4; j++) {
                int c = n0 + (tx << 2) + j;
                int sgrp = c >> 8;            // 0=q 1=k 2=v
                int h = (c >> 5) & 7, d = c & 31;
                float val = vals[j];
                size_t hp = ((size_t)(bb * 8 + h) * Pc + p) * 32 + d;
                if (sgrp == 0) {
                    g_qbf[hp] = __float2bfloat16(val * QSCALE);
                } else if (sgrp == 1) {
                    g_kbf[hp] = __float2bfloat16(val);
                } else {
                    __nv_bfloat16 hi = __float2bfloat16(val);
                    float rest = val - __bfloat162float(hi);
                    size_t idx = ((size_t)(bb * 8 + h) * 32 + d) * Pc + p;
                    g_vthi[idx] = hi;
                    g_vtlo[idx] = __float2bfloat16(rest);
                }
            }
        }
    }
}

// ---------------------------------------------------------------------------
// Fused talking-heads attention, shared-S design.
// CTA = (b, 64-row p-tile, key-split ks). 256 thr, 8 warps.
// Phase A: warp h computes S_h[64x64] -> smem bf16.
// Phase B: warp g mixes (scalar FMA) + bias + online softmax + PV (MMA).
// Smem strides: K rows 80B (20w), V/S rows 144B (36w): (s*la+lb)%32 distinct.
// ---------------------------------------------------------------------------
constexpr int KS_OFF = 0;                 // [h*64+q]*80       -> 40960 B
constexpr int VH_OFF = 40960;             // [g*32+d]*144      -> 36864 B
constexpr int VL_OFF = 77824;             // [g*32+d]*144      -> 36864 B
constexpr int SS_OFF = 114688;            // [h*64+p]*144      -> 73728 B
constexpr int SM_ATTN = 188416;

__global__ __launch_bounds__(256, 1) void attn_mma(const float* __restrict__ bias,
                                                   const float* __restrict__ wtalk) {
    extern __shared__ char smem[];

    const int tid = threadIdx.x;
    const int w = tid >> 5, lane = tid & 31;
    const int la = lane >> 2, lb = lane & 3;
    const int b = blockIdx.x & 1;
    const int ks = (blockIdx.x >> 1) & 1;
    const int p0 = (blockIdx.x >> 2) << 6;

    const __nv_bfloat16* kb = g_kbf + (size_t)(b * 8) * Pc * 32;
    const __nv_bfloat16* vhb = g_vthi + (size_t)(b * 8) * 32 * Pc;
    const __nv_bfloat16* vlb = g_vtlo + (size_t)(b * 8) * 32 * Pc;

    // Q A-fragments for head h=w, resident (order: {rowLA,kL},{row+8,kL},{rowLA,kR},{row+8,kR})
    uint32_t qf[4][2][4];
    {
        const __nv_bfloat16* qb = g_qbf + ((size_t)(b * 8 + w) * Pc + p0) * 32;
#pragma unroll
        for (int mt = 0; mt < 4; mt++)
#pragma unroll
            for (int k2 = 0; k2 < 2; k2++) {
                int d = 16 * k2 + 2 * lb;
                qf[mt][k2][0] = *(const uint32_t*)(qb + (16 * mt + la) * 32 + d);
                qf[mt][k2][1] = *(const uint32_t*)(qb + (16 * mt + la + 8) * 32 + d);
                qf[mt][k2][2] = *(const uint32_t*)(qb + (16 * mt + la) * 32 + d + 8);
                qf[mt][k2][3] = *(const uint32_t*)(qb + (16 * mt + la + 8) * 32 + d + 8);
            }
    }
    float wv[8];
#pragma unroll
    for (int hh = 0; hh < 8; hh++) wv[hh] = wtalk[w * 8 + hh];

    float o[4][4][4];
#pragma unroll
    for (int mt = 0; mt < 4; mt++)
#pragma unroll
        for (int nt = 0; nt < 4; nt++)
#pragma unroll
            for (int i = 0; i < 4; i++) o[mt][nt][i] = 0.f;
    float mr[4][2], lr[4][2];
#pragma unroll
    for (int mt = 0; mt < 4; mt++) {
        mr[mt][0] = -1e30f; mr[mt][1] = -1e30f;
        lr[mt][0] = 0.f;    lr[mt][1] = 0.f;
    }

    for (int t = 0; t < 16; t++) {
        const int q0 = (2 * t + ks) * 64;
        __syncthreads();   // previous tile fully consumed

        // ---- stage K [h][q][32d], rows 80B ----
#pragma unroll
        for (int rr = 0; rr < 2; rr++) {
            int r = tid + (rr << 8);
            int h = r >> 6, q = r & 63;
            const __nv_bfloat16* src = kb + ((size_t)h * Pc + q0 + q) * 32;
            char* dst = smem + KS_OFF + r * 80;
#pragma unroll
            for (int j = 0; j < 4; j++)
                *(uint4*)(dst + j * 16) = *(const uint4*)(src + j * 8);
        }
        // ---- stage V hi/lo [g][d][64q], rows 144B ----
        {
            const __nv_bfloat16* srcH = vhb + (size_t)tid * Pc + q0;
            const __nv_bfloat16* srcL = vlb + (size_t)tid * Pc + q0;
            char* dstH = smem + VH_OFF + tid * 144;
            char* dstL = smem + VL_OFF + tid * 144;
#pragma unroll
            for (int j = 0; j < 8; j++) {
                *(uint4*)(dstH + j * 16) = *(const uint4*)(srcH + j * 8);
                *(uint4*)(dstL + j * 16) = *(const uint4*)(srcL + j * 8);
            }
        }
        __syncthreads();

        // ---- phase A: S_h = Q_h @ K_h^T (warp = head), K=32 ----
#pragma unroll
        for (int mt = 0; mt < 4; mt++) {
#pragma unroll
            for (int nt = 0; nt < 8; nt++) {
                float cc[4] = {0.f, 0.f, 0.f, 0.f};
#pragma unroll
                for (int k2 = 0; k2 < 2; k2++) {
                    const char* kp =
                        smem + KS_OFF + (w * 64 + 8 * nt + la) * 80 + lb * 4 + k2 * 32;
                    uint32_t bb[2];
                    bb[0] = *(const uint32_t*)(kp);
                    bb[1] = *(const uint32_t*)(kp + 16);
                    mma16816(cc, qf[mt][k2], bb);
                }
                char* sp =
                    smem + SS_OFF + (w * 64 + 16 * mt + la) * 144 + (4 * nt + lb) * 4;
                *(uint32_t*)sp = packbf(cc[0], cc[1]);
                *(uint32_t*)(sp + 8 * 144) = packbf(cc[2], cc[3]);
            }
        }
        __syncthreads();

        // ---- phase B: mix + bias + online softmax + PV (warp = g) ----
#pragma unroll
        for (int mt = 0; mt < 4; mt++) {
            const int rA = 16 * mt + la, rB = rA + 8;
            float TA[16], TB[16];
            {
                const float* bpA =
                    bias + ((size_t)w * Pc + p0 + rA) * Pc + q0 + 2 * lb;
                const float* bpB = bpA + 8 * Pc;
#pragma unroll
                for (int kc = 0; kc < 4; kc++) {
                    float2 u = *(const float2*)(bpA + 16 * kc);
                    float2 u2 = *(const float2*)(bpA + 16 * kc + 8);
                    TA[4 * kc + 0] = u.x;  TA[4 * kc + 1] = u.y;
                    TA[4 * kc + 2] = u2.x; TA[4 * kc + 3] = u2.y;
                    float2 v = *(const float2*)(bpB + 16 * kc);
                    float2 v2 = *(const float2*)(bpB + 16 * kc + 8);
                    TB[4 * kc + 0] = v.x;  TB[4 * kc + 1] = v.y;
                    TB[4 * kc + 2] = v2.x; TB[4 * kc + 3] = v2.y;
                }
            }
            // talking-heads mix: T += sum_h w[h]*S_h (scalar pipe)
#pragma unroll
            for (int hh = 0; hh < 8; hh++) {
                const float wgt = wv[hh];
                const char* s0 = smem + SS_OFF + (hh * 64 + rA) * 144 + lb * 4;
                const char* s1 = smem + SS_OFF + (hh * 64 + rB) * 144 + lb * 4;
#pragma unroll
                for (int kc = 0; kc < 4; kc++) {
                    uint32_t a0 = *(const uint32_t*)(s0 + kc * 32);
                    uint32_t a1 = *(const uint32_t*)(s0 + kc * 32 + 16);
                    uint32_t b0 = *(const uint32_t*)(s1 + kc * 32);
                    uint32_t b1 = *(const uint32_t*)(s1 + kc * 32 + 16);
                    TA[4 * kc + 0] = fmaf(wgt, bflo(a0), TA[4 * kc + 0]);
                    TA[4 * kc + 1] = fmaf(wgt, bfhi(a0), TA[4 * kc + 1]);
                    TA[4 * kc + 2] = fmaf(wgt, bflo(a1), TA[4 * kc + 2]);
                    TA[4 * kc + 3] = fmaf(wgt, bfhi(a1), TA[4 * kc + 3]);
                    TB[4 * kc + 0] = fmaf(wgt, bflo(b0), TB[4 * kc + 0]);
                    TB[4 * kc + 1] = fmaf(wgt, bfhi(b0), TB[4 * kc + 1]);
                    TB[4 * kc + 2] = fmaf(wgt, bflo(b1), TB[4 * kc + 2]);
                    TB[4 * kc + 3] = fmaf(wgt, bfhi(b1), TB[4 * kc + 3]);
                }
            }
            // online softmax rows rA (lanes same la reduce over lb)
            float mxA = TA[0], mxB = TB[0];
#pragma unroll
            for (int i = 1; i < 16; i++) {
                mxA = fmaxf(mxA, TA[i]);
                mxB = fmaxf(mxB, TB[i]);
            }
            mxA = fmaxf(mxA, __shfl_xor_sync(0xffffffffu, mxA, 1));
            mxA = fmaxf(mxA, __shfl_xor_sync(0xffffffffu, mxA, 2));
            mxB = fmaxf(mxB, __shfl_xor_sync(0xffffffffu, mxB, 1));
            mxB = fmaxf(mxB, __shfl_xor_sync(0xffffffffu, mxB, 2));
            mxA = fmaxf(mxA, mr[mt][0]);
            mxB = fmaxf(mxB, mr[mt][1]);
            const float scA = __expf(mr[mt][0] - mxA);
            const float scB = __expf(mr[mt][1] - mxB);
            mr[mt][0] = mxA; mr[mt][1] = mxB;
            lr[mt][0] *= scA; lr[mt][1] *= scB;
#pragma unroll
            for (int nt = 0; nt < 4; nt++) {
                o[mt][nt][0] *= scA; o[mt][nt][1] *= scA;
                o[mt][nt][2] *= scB; o[mt][nt][3] *= scB;
            }
            float lsA = 0.f, lsB = 0.f;
#pragma unroll
            for (int i = 0; i < 16; i++) {
                TA[i] = __expf(TA[i] - mxA); lsA += TA[i];
                TB[i] = __expf(TB[i] - mxB); lsB += TB[i];
            }
            lr[mt][0] += lsA; lr[mt][1] += lsB;

            // PV: O += Phi@Vhi + Phi@Vlo + Plo@Vhi
#pragma unroll
            for (int kc = 0; kc < 4; kc++) {
                uint32_t phi[4], plo[4];
                phi[0] = packbf(TA[4 * kc + 0], TA[4 * kc + 1]);
                phi[1] = packbf(TB[4 * kc + 0], TB[4 * kc + 1]);
                phi[2] = packbf(TA[4 * kc + 2], TA[4 * kc + 3]);
                phi[3] = packbf(TB[4 * kc + 2], TB[4 * kc + 3]);
                plo[0] = packbf(TA[4 * kc + 0] - bfround(TA[4 * kc + 0]),
                                TA[4 * kc + 1] - bfround(TA[4 * kc + 1]));
                plo[1] = packbf(TB[4 * kc + 0] - bfround(TB[4 * kc + 0]),
                                TB[4 * kc + 1] - bfround(TB[4 * kc + 1]));
                plo[2] = packbf(TA[4 * kc + 2] - bfround(TA[4 * kc + 2]),
                                TA[4 * kc + 3] - bfround(TA[4 * kc + 3]));
                plo[3] = packbf(TB[4 * kc + 2] - bfround(TB[4 * kc + 2]),
                                TB[4 * kc + 3] - bfround(TB[4 * kc + 3]));
#pragma unroll
                for (int nt = 0; nt < 4; nt++) {
                    const int vrow = (w * 32 + 8 * nt + la) * 144 + lb * 4 + kc * 32;
                    uint32_t bh[2], bl[2];
                    bh[0] = *(const uint32_t*)(smem + VH_OFF + vrow);
                    bh[1] = *(const uint32_t*)(smem + VH_OFF + vrow + 16);
                    bl[0] = *(const uint32_t*)(smem + VL_OFF + vrow);
                    bl[1] = *(const uint32_t*)(smem + VL_OFF + vrow + 16);
                    mma16816(o[mt][nt], phi, bh);
                    mma16816(o[mt][nt], phi, bl);
                    mma16816(o[mt][nt], plo, bh);
                }
            }
        }
    }

    // ---- epilogue: write O partials + (m,l) per row to scratch ----
#pragma unroll
    for (int mt = 0; mt < 4; mt++) {
        float lA = lr[mt][0];
        lA += __shfl_xor_sync(0xffffffffu, lA, 1);
        lA += __shfl_xor_sync(0xffffffffu, lA, 2);
        float lB = lr[mt][1];
        lB += __shfl_xor_sync(0xffffffffu, lB, 1);
        lB += __shfl_xor_sync(0xffffffffu, lB, 2);
        const int rA = p0 + 16 * mt + la;
        float* obase = g_oscr + ((size_t)(ks * 2 + b) * Pc + rA) * 256 + w * 32 + 2 * lb;
#pragma unroll
        for (int nt = 0; nt < 4; nt++) {
            *(float2*)(obase + 8 * nt) = make_float2(o[mt][nt][0], o[mt][nt][1]);
            *(float2*)(obase + 8 * 256 + 8 * nt) = make_float2(o[mt][nt][2], o[mt][nt][3]);
        }
        if (lb == 0) {
            size_t mlb = ((size_t)(ks * 2 + b) * 8 + w) * Pc;
            g_mlscr[mlb + rA] = make_float2(mr[mt][0], lA);
            g_mlscr[mlb + rA + 8] = make_float2(mr[mt][1], lB);
        }
    }
}

// ---------------------------------------------------------------------------
// Key-split merge: ctxt = (e0*O0 + e1*O1) / (e0*l0 + e1*l1)
// ---------------------------------------------------------------------------
__global__ __launch_bounds__(256) void merge_k() {
    int idx = blockIdx.x * 256 + threadIdx.x;   // 262144 float4 units
    int c4 = idx & 63;
    int row = idx >> 6;                          // b*2048 + p
    int g = c4 >> 3;
    int b = row >> 11, p = row & 2047;
    float2 ml0 = g_mlscr[((size_t)(b * 8) + g) * Pc + p];
    float2 ml1 = g_mlscr[((size_t)((2 + b) * 8) + g) * Pc + p];
    float m = fmaxf(ml0.x, ml1.x);
    float e0 = __expf(ml0.x - m), e1 = __expf(ml1.x - m);
    float li = 1.0f / (e0 * ml0.y + e1 * ml1.y);
    e0 *= li; e1 *= li;
    const float4 a = *(const float4*)(g_oscr + (size_t)row * 256 + c4 * 4);
    const float4 c = *(const float4*)(g_oscr + (size_t)(Bc * Pc + row) * 256 + c4 * 4);
    float4 r;
    r.x = e0 * a.x + e1 * c.x;
    r.y = e0 * a.y + e1 * c.y;
    r.z = e0 * a.z + e1 * c.z;
    r.w = e0 * a.w + e1 * c.w;
    *(float4*)(g_ctxt + (size_t)row * 256 + c4 * 4) = r;
}

// ---------------------------------------------------------------------------
extern "C" void kernel_launch(void* const* d_in, const int* in_sizes, int n_in,
                              void* d_out, int out_size) {
    (void)in_sizes; (void)n_in; (void)out_size;
    const float* x     = (const float*)d_in[0];
    const float* bias  = (const float*)d_in[1];
    const float* wqkv  = (const float*)d_in[2];
    const float* wtalk = (const float*)d_in[3];
    const float* wproj = (const float*)d_in[4];
    float* out = (float*)d_out;

    cudaFuncSetAttribute(attn_mma, cudaFuncAttributeMaxDynamicSharedMemorySize,
                         SM_ATTN);

    void* ctxt_ptr = nullptr;
    cudaGetSymbolAddress(&ctxt_ptr, g_ctxt);

    // 1) QKV projection + per-head bf16 epilogue
    gemm_nt<1><<<dim3(64, 12), 256>>>(x, wqkv, nullptr, Bc * Pc, 3 * Hc * DFc, 128);

    // 2) fused attention (shared S, mix on fma pipe, PV on tensor pipe)
    attn_mma<<<Bc * 2 * (Pc / 64), 256, SM_ATTN>>>(bias, wtalk);

    // 3) key-split merge -> g_ctxt
    merge_k<<<1024, 256>>>();

    // 4) output projection
    gemm_nt<0><<<dim3(64, 2), 256>>>((const float*)ctxt_ptr, wproj, out,
                                     Bc * Pc, 128, Hc * DFc);
}

// round 12
// speedup vs baseline: 1.0104x; 1.0104x over previous
#include <cuda_runtime.h>
#include <cuda_bf16.h>
#include <cstdint>

#define DEV_INLINE __device__ __forceinline__

// ------------------------------- f32x2 helpers (GEMM kernels) -------------
struct U64F2 { union { unsigned long long u; float2 f; }; };
DEV_INLINE U64F2 f2fma(U64F2 a, U64F2 b, U64F2 c) {
    U64F2 d;
    asm("fma.rn.f32x2 %0, %1, %2, %3;" : "=l"(d.u) : "l"(a.u), "l"(b.u), "l"(c.u));
    return d;
}
DEV_INLINE U64F2 pk2(float v) {
    U64F2 d;
    asm("mov.b64 %0, {%1, %1};" : "=l"(d.u) : "f"(v));
    return d;
}

// ------------------------------- mma.sync helpers -------------------------
DEV_INLINE void mma16816(float* c, const uint32_t* a, const uint32_t* b) {
    asm volatile(
        "mma.sync.aligned.m16n8k16.row.col.f32.bf16.bf16.f32 "
        "{%0,%1,%2,%3}, {%4,%5,%6,%7}, {%8,%9}, {%0,%1,%2,%3};"
        : "+f"(c[0]), "+f"(c[1]), "+f"(c[2]), "+f"(c[3])
        : "r"(a[0]), "r"(a[1]), "r"(a[2]), "r"(a[3]), "r"(b[0]), "r"(b[1]));
}
DEV_INLINE uint32_t packbf(float lo, float hi) {  // low half = lo
    uint32_t r;
    asm("cvt.rn.bf16x2.f32 %0, %1, %2;" : "=r"(r) : "f"(hi), "f"(lo));
    return r;
}
DEV_INLINE float bfround(float x) {
    return __bfloat162float(__float2bfloat16(x));
}
DEV_INLINE float bflo(uint32_t u) { return __uint_as_float(u << 16); }
DEV_INLINE float bfhi(uint32_t u) { return __uint_as_float(u & 0xFFFF0000u); }

// ------------------------------- problem constants ------------------------
constexpr int Bc = 2, Pc = 2048, Hc = 8, DFc = 32;
constexpr float QSCALE = 0.17677669529663687f;  // 1/sqrt(32)

__device__ __align__(16) __nv_bfloat16 g_qbf[Bc * 8 * Pc * 32];   // [b,h,p,d] scaled
__device__ __align__(16) __nv_bfloat16 g_kbf[Bc * 8 * Pc * 32];   // [b,h,q,d]
__device__ __align__(16) __nv_bfloat16 g_vthi[Bc * 8 * 32 * Pc];  // [b,h,d,q]
__device__ __align__(16) __nv_bfloat16 g_vtlo[Bc * 8 * 32 * Pc];
__device__ __align__(16) float g_ctxt[Bc * Pc * 256];
__device__ __align__(16) float g_oscr[2 * Bc * Pc * 256];         // [ks,b,p,256]
__device__ __align__(16) float2 g_mlscr[2 * Bc * 8 * Pc];         // [ks,b,g,p]

// ---------------------------------------------------------------------------
// GEMM: C = A[M,K] @ Bw[N,K]^T. EPI=1: per-head q/k bf16 + v hi/lo transpose.
// ---------------------------------------------------------------------------
template <int EPI>
__global__ __launch_bounds__(256) void gemm_nt(const float* __restrict__ A,
                                               const float* __restrict__ Bw,
                                               float* __restrict__ C,
                                               int M, int N, int K) {
    __shared__ __align__(16) float As[64][68];
    __shared__ __align__(16) float Bs[64][68];

    const int tid = threadIdx.x;
    const int tx = tid & 15, ty = tid >> 4;
    const int m0 = blockIdx.x << 6, n0 = blockIdx.y << 6;
    const int bn = tid & 63;
    const int bk = (tid >> 6) << 4;

    U64F2 acc[4][2];
#pragma unroll
    for (int i = 0; i < 4; i++) {
        acc[i][0].f = make_float2(0.f, 0.f);
        acc[i][1].f = make_float2(0.f, 0.f);
    }

    for (int kc = 0; kc < K; kc += 64) {
#pragma unroll
        for (int i = 0; i < 4; i++) {
            int v = tid + (i << 8);
            int r = v >> 4, k4 = v & 15;
            *(float4*)&As[r][k4 << 2] =
                *(const float4*)&A[(size_t)(m0 + r) * K + kc + (k4 << 2)];
        }
#pragma unroll
        for (int c4 = 0; c4 < 4; c4++) {
            float4 bv = *(const float4*)&Bw[(size_t)(n0 + bn) * K + kc + bk + (c4 << 2)];
            Bs[bk + (c4 << 2) + 0][bn] = bv.x;
            Bs[bk + (c4 << 2) + 1][bn] = bv.y;
            Bs[bk + (c4 << 2) + 2][bn] = bv.z;
            Bs[bk + (c4 << 2) + 3][bn] = bv.w;
        }
        __syncthreads();
#pragma unroll 8
        for (int kk = 0; kk < 64; kk++) {
            float4 b01 = *(const float4*)&Bs[kk][tx << 2];
            U64F2 b0, b1;
            b0.f = make_float2(b01.x, b01.y);
            b1.f = make_float2(b01.z, b01.w);
#pragma unroll
            for (int i = 0; i < 4; i++) {
                U64F2 a2 = pk2(As[(ty << 2) + i][kk]);
                acc[i][0] = f2fma(a2, b0, acc[i][0]);
                acc[i][1] = f2fma(a2, b1, acc[i][1]);
            }
        }
        __syncthreads();
    }

    if (EPI == 0) {
#pragma unroll
        for (int i = 0; i < 4; i++) {
            float4 vout;
            vout.x = acc[i][0].f.x; vout.y = acc[i][0].f.y;
            vout.z = acc[i][1].f.x; vout.w = acc[i][1].f.y;
            *(float4*)&C[(size_t)(m0 + (ty << 2) + i) * N + n0 + (tx << 2)] = vout;
        }
    } else {
#pragma unroll
        for (int i = 0; i < 4; i++) {
            float vals[4] = {acc[i][0].f.x, acc[i][0].f.y, acc[i][1].f.x, acc[i][1].f.y};
            int r = m0 + (ty << 2) + i;
            int bb = r >> 11, p = r & 2047;
#pragma unroll
            for (int j = 0; j < 4; j++) {
                int c = n0 + (tx << 2) + j;
                int sgrp = c >> 8;            // 0=q 1=k 2=v
                int h = (c >> 5) & 7, d = c & 31;
                float val = vals[j];
                size_t hp = ((size_t)(bb * 8 + h) * Pc + p) * 32 + d;
                if (sgrp == 0) {
                    g_qbf[hp] = __float2bfloat16(val * QSCALE);
                } else if (sgrp == 1) {
                    g_kbf[hp] = __float2bfloat16(val);
                } else {
                    __nv_bfloat16 hi = __float2bfloat16(val);
                    float rest = val - __bfloat162float(hi);
                    size_t idx = ((size_t)(bb * 8 + h) * 32 + d) * Pc + p;
                    g_vthi[idx] = hi;
                    g_vtlo[idx] = __float2bfloat16(rest);
                }
            }
        }
    }
}

// ---------------------------------------------------------------------------
// Fused talking-heads attention, shared-S design sized for 2 CTAs/SM.
// CTA = (b, 32-row p-tile, key-split ks of 2). 256 thr, 8 warps.
// Phase A: warp h computes S_h[32x32] -> smem bf16.
// Phase B: warp g mixes (scalar FMA) + bias + online softmax + PV (MMA).
// Rows 80B (20 words): la*20+lb mod 32 hits all banks -> conflict-free.
// ---------------------------------------------------------------------------
constexpr int KS_OFF = 0;                 // [h*32+q]*80  -> 20480 B
constexpr int VH_OFF = 20480;             // [g*32+d]*80  -> 20480 B
constexpr int VL_OFF = 40960;             // [g*32+d]*80  -> 20480 B
constexpr int SS_OFF = 61440;             // [h*32+p]*80  -> 20480 B
constexpr int SM_ATTN = 81920;

__global__ __launch_bounds__(256, 2) void attn_mma(const float* __restrict__ bias,
                                                   const float* __restrict__ wtalk) {
    extern __shared__ char smem[];

    const int tid = threadIdx.x;
    const int w = tid >> 5, lane = tid & 31;
    const int la = lane >> 2, lb = lane & 3;
    const int b = blockIdx.x & 1;
    const int ks = (blockIdx.x >> 1) & 1;
    const int p0 = (blockIdx.x >> 2) << 5;

    const __nv_bfloat16* kb = g_kbf + (size_t)(b * 8) * Pc * 32;
    const __nv_bfloat16* vhb = g_vthi + (size_t)(b * 8) * 32 * Pc;
    const __nv_bfloat16* vlb = g_vtlo + (size_t)(b * 8) * 32 * Pc;

    // Q A-fragments, head h=w, rows p0..p0+31 (order {rLA,kL},{r+8,kL},{rLA,kR},{r+8,kR})
    uint32_t qf[2][2][4];
    {
        const __nv_bfloat16* qb = g_qbf + ((size_t)(b * 8 + w) * Pc + p0) * 32;
#pragma unroll
        for (int mt = 0; mt < 2; mt++)
#pragma unroll
            for (int k2 = 0; k2 < 2; k2++) {
                int d = 16 * k2 + 2 * lb;
                qf[mt][k2][0] = *(const uint32_t*)(qb + (16 * mt + la) * 32 + d);
                qf[mt][k2][1] = *(const uint32_t*)(qb + (16 * mt + la + 8) * 32 + d);
                qf[mt][k2][2] = *(const uint32_t*)(qb + (16 * mt + la) * 32 + d + 8);
                qf[mt][k2][3] = *(const uint32_t*)(qb + (16 * mt + la + 8) * 32 + d + 8);
            }
    }
    float wv[8];
#pragma unroll
    for (int hh = 0; hh < 8; hh++) wv[hh] = wtalk[w * 8 + hh];

    float o[2][4][4];
#pragma unroll
    for (int mt = 0; mt < 2; mt++)
#pragma unroll
        for (int nt = 0; nt < 4; nt++)
#pragma unroll
            for (int i = 0; i < 4; i++) o[mt][nt][i] = 0.f;
    float mr[2][2], lr[2][2];
#pragma unroll
    for (int mt = 0; mt < 2; mt++) {
        mr[mt][0] = -1e30f; mr[mt][1] = -1e30f;
        lr[mt][0] = 0.f;    lr[mt][1] = 0.f;
    }

    for (int t = 0; t < 32; t++) {
        const int q0 = (2 * t + ks) * 32;
        __syncthreads();   // previous tile fully consumed

        // ---- stage K [8h][32q][32d] rows 80B (1 row / thread, 64B each) ----
        {
            int h = tid >> 5, q = tid & 31;
            const __nv_bfloat16* src = kb + ((size_t)h * Pc + q0 + q) * 32;
            char* dst = smem + KS_OFF + tid * 80;
#pragma unroll
            for (int j = 0; j < 4; j++)
                *(uint4*)(dst + j * 16) = *(const uint4*)(src + j * 8);
        }
        // ---- stage V hi/lo [8g][32d][32q] rows 80B ----
        {
            const __nv_bfloat16* srcH = vhb + (size_t)tid * Pc + q0;
            const __nv_bfloat16* srcL = vlb + (size_t)tid * Pc + q0;
            char* dstH = smem + VH_OFF + tid * 80;
            char* dstL = smem + VL_OFF + tid * 80;
#pragma unroll
            for (int j = 0; j < 4; j++) {
                *(uint4*)(dstH + j * 16) = *(const uint4*)(srcH + j * 8);
                *(uint4*)(dstL + j * 16) = *(const uint4*)(srcL + j * 8);
            }
        }
        __syncthreads();

        // ---- phase A: S_h = Q_h @ K_h^T (warp = head), K=32 ----
#pragma unroll
        for (int mt = 0; mt < 2; mt++) {
#pragma unroll
            for (int nt = 0; nt < 4; nt++) {
                float cc[4] = {0.f, 0.f, 0.f, 0.f};
#pragma unroll
                for (int k2 = 0; k2 < 2; k2++) {
                    const char* kp =
                        smem + KS_OFF + (w * 32 + 8 * nt + la) * 80 + lb * 4 + k2 * 32;
                    uint32_t bb[2];
                    bb[0] = *(const uint32_t*)(kp);
                    bb[1] = *(const uint32_t*)(kp + 16);
                    mma16816(cc, qf[mt][k2], bb);
                }
                char* sp =
                    smem + SS_OFF + (w * 32 + 16 * mt + la) * 80 + (4 * nt + lb) * 4;
                *(uint32_t*)sp = packbf(cc[0], cc[1]);
                *(uint32_t*)(sp + 8 * 80) = packbf(cc[2], cc[3]);
            }
        }
        __syncthreads();

        // ---- phase B: mix + bias + online softmax + PV (warp = g) ----
#pragma unroll
        for (int mt = 0; mt < 2; mt++) {
            const int rA = 16 * mt + la;
            float TA[8], TB[8];
            {
                const float* bpA =
                    bias + ((size_t)w * Pc + p0 + rA) * Pc + q0 + 2 * lb;
                const float* bpB = bpA + 8 * Pc;
#pragma unroll
                for (int kc = 0; kc < 2; kc++) {
                    float2 u = *(const float2*)(bpA + 16 * kc);
                    float2 u2 = *(const float2*)(bpA + 16 * kc + 8);
                    TA[4 * kc + 0] = u.x;  TA[4 * kc + 1] = u.y;
                    TA[4 * kc + 2] = u2.x; TA[4 * kc + 3] = u2.y;
                    float2 v = *(const float2*)(bpB + 16 * kc);
                    float2 v2 = *(const float2*)(bpB + 16 * kc + 8);
                    TB[4 * kc + 0] = v.x;  TB[4 * kc + 1] = v.y;
                    TB[4 * kc + 2] = v2.x; TB[4 * kc + 3] = v2.y;
                }
            }
            // talking-heads mix: T += sum_h w[h]*S_h (scalar pipe)
#pragma unroll
            for (int hh = 0; hh < 8; hh++) {
                const float wgt = wv[hh];
                const char* s0 = smem + SS_OFF + (hh * 32 + rA) * 80 + lb * 4;
                const char* s1 = smem + SS_OFF + (hh * 32 + rA + 8) * 80 + lb * 4;
#pragma unroll
                for (int kc = 0; kc < 2; kc++) {
                    uint32_t a0 = *(const uint32_t*)(s0 + kc * 32);
                    uint32_t a1 = *(const uint32_t*)(s0 + kc * 32 + 16);
                    uint32_t b0 = *(const uint32_t*)(s1 + kc * 32);
                    uint32_t b1 = *(const uint32_t*)(s1 + kc * 32 + 16);
                    TA[4 * kc + 0] = fmaf(wgt, bflo(a0), TA[4 * kc + 0]);
                    TA[4 * kc + 1] = fmaf(wgt, bfhi(a0), TA[4 * kc + 1]);
                    TA[4 * kc + 2] = fmaf(wgt, bflo(a1), TA[4 * kc + 2]);
                    TA[4 * kc + 3] = fmaf(wgt, bfhi(a1), TA[4 * kc + 3]);
                    TB[4 * kc + 0] = fmaf(wgt, bflo(b0), TB[4 * kc + 0]);
                    TB[4 * kc + 1] = fmaf(wgt, bfhi(b0), TB[4 * kc + 1]);
                    TB[4 * kc + 2] = fmaf(wgt, bflo(b1), TB[4 * kc + 2]);
                    TB[4 * kc + 3] = fmaf(wgt, bfhi(b1), TB[4 * kc + 3]);
                }
            }
            // online softmax (rows rA, rA+8); reduce over lb quad
            float mxA = TA[0], mxB = TB[0];
#pragma unroll
            for (int i = 1; i < 8; i++) {
                mxA = fmaxf(mxA, TA[i]);
                mxB = fmaxf(mxB, TB[i]);
            }
            mxA = fmaxf(mxA, __shfl_xor_sync(0xffffffffu, mxA, 1));
            mxA = fmaxf(mxA, __shfl_xor_sync(0xffffffffu, mxA, 2));
            mxB = fmaxf(mxB, __shfl_xor_sync(0xffffffffu, mxB, 1));
            mxB = fmaxf(mxB, __shfl_xor_sync(0xffffffffu, mxB, 2));
            mxA = fmaxf(mxA, mr[mt][0]);
            mxB = fmaxf(mxB, mr[mt][1]);
            const float scA = __expf(mr[mt][0] - mxA);
            const float scB = __expf(mr[mt][1] - mxB);
            mr[mt][0] = mxA; mr[mt][1] = mxB;
            lr[mt][0] *= scA; lr[mt][1] *= scB;
#pragma unroll
            for (int nt = 0; nt < 4; nt++) {
                o[mt][nt][0] *= scA; o[mt][nt][1] *= scA;
                o[mt][nt][2] *= scB; o[mt][nt][3] *= scB;
            }
            float lsA = 0.f, lsB = 0.f;
#pragma unroll
            for (int i = 0; i < 8; i++) {
                TA[i] = __expf(TA[i] - mxA); lsA += TA[i];
                TB[i] = __expf(TB[i] - mxB); lsB += TB[i];
            }
            lr[mt][0] += lsA; lr[mt][1] += lsB;

            // PV: O += Phi@Vhi + Phi@Vlo + Plo@Vhi
#pragma unroll
            for (int kc = 0; kc < 2; kc++) {
                uint32_t phi[4], plo[4];
                phi[0] = packbf(TA[4 * kc + 0], TA[4 * kc + 1]);
                phi[1] = packbf(TB[4 * kc + 0], TB[4 * kc + 1]);
                phi[2] = packbf(TA[4 * kc + 2], TA[4 * kc + 3]);
                phi[3] = packbf(TB[4 * kc + 2], TB[4 * kc + 3]);
                plo[0] = packbf(TA[4 * kc + 0] - bfround(TA[4 * kc + 0]),
                                TA[4 * kc + 1] - bfround(TA[4 * kc + 1]));
                plo[1] = packbf(TB[4 * kc + 0] - bfround(TB[4 * kc + 0]),
                                TB[4 * kc + 1] - bfround(TB[4 * kc + 1]));
                plo[2] = packbf(TA[4 * kc + 2] - bfround(TA[4 * kc + 2]),
                                TA[4 * kc + 3] - bfround(TA[4 * kc + 3]));
                plo[3] = packbf(TB[4 * kc + 2] - bfround(TB[4 * kc + 2]),
                                TB[4 * kc + 3] - bfround(TB[4 * kc + 3]));
#pragma unroll
                for (int nt = 0; nt < 4; nt++) {
                    const int vrow = (w * 32 + 8 * nt + la) * 80 + lb * 4 + kc * 32;
                    uint32_t bh[2], bl[2];
                    bh[0] = *(const uint32_t*)(smem + VH_OFF + vrow);
                    bh[1] = *(const uint32_t*)(smem + VH_OFF + vrow + 16);
                    bl[0] = *(const uint32_t*)(smem + VL_OFF + vrow);
                    bl[1] = *(const uint32_t*)(smem + VL_OFF + vrow + 16);
                    mma16816(o[mt][nt], phi, bh);
                    mma16816(o[mt][nt], phi, bl);
                    mma16816(o[mt][nt], plo, bh);
                }
            }
        }
    }

    // ---- epilogue: write O partials + (m,l) per row to scratch ----
#pragma unroll
    for (int mt = 0; mt < 2; mt++) {
        float lA = lr[mt][0];
        lA += __shfl_xor_sync(0xffffffffu, lA, 1);
        lA += __shfl_xor_sync(0xffffffffu, lA, 2);
        float lB = lr[mt][1];
        lB += __shfl_xor_sync(0xffffffffu, lB, 1);
        lB += __shfl_xor_sync(0xffffffffu, lB, 2);
        const int rA = p0 + 16 * mt + la;
        float* obase = g_oscr + ((size_t)(ks * 2 + b) * Pc + rA) * 256 + w * 32 + 2 * lb;
#pragma unroll
        for (int nt = 0; nt < 4; nt++) {
            *(float2*)(obase + 8 * nt) = make_float2(o[mt][nt][0], o[mt][nt][1]);
            *(float2*)(obase + 8 * 256 + 8 * nt) = make_float2(o[mt][nt][2], o[mt][nt][3]);
        }
        if (lb == 0) {
            size_t mlb = ((size_t)(ks * 2 + b) * 8 + w) * Pc;
            g_mlscr[mlb + rA] = make_float2(mr[mt][0], lA);
            g_mlscr[mlb + rA + 8] = make_float2(mr[mt][1], lB);
        }
    }
}

// ---------------------------------------------------------------------------
// Key-split merge: ctxt = (e0*O0 + e1*O1) / (e0*l0 + e1*l1)
// ---------------------------------------------------------------------------
__global__ __launch_bounds__(256) void merge_k() {
    int idx = blockIdx.x * 256 + threadIdx.x;   // 262144 float4 units
    int c4 = idx & 63;
    int row = idx >> 6;                          // b*2048 + p
    int g = c4 >> 3;
    int b = row >> 11, p = row & 2047;
    float2 ml0 = g_mlscr[((size_t)(b * 8) + g) * Pc + p];
    float2 ml1 = g_mlscr[((size_t)((2 + b) * 8) + g) * Pc + p];
    float m = fmaxf(ml0.x, ml1.x);
    float e0 = __expf(ml0.x - m), e1 = __expf(ml1.x - m);
    float li = 1.0f / (e0 * ml0.y + e1 * ml1.y);
    e0 *= li; e1 *= li;
    const float4 a = *(const float4*)(g_oscr + (size_t)row * 256 + c4 * 4);
    const float4 c = *(const float4*)(g_oscr + (size_t)(Bc * Pc + row) * 256 + c4 * 4);
    float4 r;
    r.x = e0 * a.x + e1 * c.x;
    r.y = e0 * a.y + e1 * c.y;
    r.z = e0 * a.z + e1 * c.z;
    r.w = e0 * a.w + e1 * c.w;
    *(float4*)(g_ctxt + (size_t)row * 256 + c4 * 4) = r;
}

// ---------------------------------------------------------------------------
extern "C" void kernel_launch(void* const* d_in, const int* in_sizes, int n_in,
                              void* d_out, int out_size) {
    (void)in_sizes; (void)n_in; (void)out_size;
    const float* x     = (const float*)d_in[0];
    const float* bias  = (const float*)d_in[1];
    const float* wqkv  = (const float*)d_in[2];
    const float* wtalk = (const float*)d_in[3];
    const float* wproj = (const float*)d_in[4];
    float* out = (float*)d_out;

    cudaFuncSetAttribute(attn_mma, cudaFuncAttributeMaxDynamicSharedMemorySize,
                         SM_ATTN);

    void* ctxt_ptr = nullptr;
    cudaGetSymbolAddress(&ctxt_ptr, g_ctxt);

    // 1) QKV projection + per-head bf16 epilogue
    gemm_nt<1><<<dim3(64, 12), 256>>>(x, wqkv, nullptr, Bc * Pc, 3 * Hc * DFc, 128);

    // 2) fused attention (shared S, 2 CTAs/SM) -> partials
    attn_mma<<<Bc * 2 * (Pc / 32), 256, SM_ATTN>>>(bias, wtalk);

    // 3) key-split merge -> g_ctxt
    merge_k<<<1024, 256>>>();

    // 4) output projection
    gemm_nt<0><<<dim3(64, 2), 256>>>((const float*)ctxt_ptr, wproj, out,
                                     Bc * Pc, 128, Hc * DFc);
}

// round 13
// speedup vs baseline: 1.4696x; 1.4544x over previous
#include <cuda_runtime.h>
#include <cuda_fp16.h>
#include <cstdint>

#define DEV_INLINE __device__ __forceinline__

// ------------------------------- f32x2 helpers (GEMM kernels) -------------
struct U64F2 { union { unsigned long long u; float2 f; }; };
DEV_INLINE U64F2 f2fma(U64F2 a, U64F2 b, U64F2 c) {
    U64F2 d;
    asm("fma.rn.f32x2 %0, %1, %2, %3;" : "=l"(d.u) : "l"(a.u), "l"(b.u), "l"(c.u));
    return d;
}
DEV_INLINE U64F2 pk2(float v) {
    U64F2 d;
    asm("mov.b64 %0, {%1, %1};" : "=l"(d.u) : "f"(v));
    return d;
}

// ------------------------------- mma helpers (fp16) -----------------------
DEV_INLINE void mma16816h(float* c, const uint32_t* a, const uint32_t* b) {
    asm volatile(
        "mma.sync.aligned.m16n8k16.row.col.f32.f16.f16.f32 "
        "{%0,%1,%2,%3}, {%4,%5,%6,%7}, {%8,%9}, {%0,%1,%2,%3};"
        : "+f"(c[0]), "+f"(c[1]), "+f"(c[2]), "+f"(c[3])
        : "r"(a[0]), "r"(a[1]), "r"(a[2]), "r"(a[3]), "r"(b[0]), "r"(b[1]));
}
DEV_INLINE void mma16808h(float* c, const uint32_t* a, uint32_t b) {
    asm volatile(
        "mma.sync.aligned.m16n8k8.row.col.f32.f16.f16.f32 "
        "{%0,%1,%2,%3}, {%4,%5}, {%6}, {%0,%1,%2,%3};"
        : "+f"(c[0]), "+f"(c[1]), "+f"(c[2]), "+f"(c[3])
        : "r"(a[0]), "r"(a[1]), "r"(b));
}
DEV_INLINE uint32_t packh(float lo, float hi) {  // low half = lo
    uint32_t r;
    asm("cvt.rn.f16x2.f32 %0, %1, %2;" : "=r"(r) : "f"(hi), "f"(lo));
    return r;
}

// ------------------------------- problem constants ------------------------
constexpr int Bc = 2, Pc = 2048, Hc = 8, DFc = 32;
constexpr float QSCALE = 0.17677669529663687f;  // 1/sqrt(32)

__device__ __align__(16) __half g_qh[Bc * 8 * Pc * 32];   // [b,h,p,d] scaled
__device__ __align__(16) __half g_kh[Bc * 8 * Pc * 32];   // [b,h,q,d]
__device__ __align__(16) __half g_vt[Bc * 8 * 32 * Pc];   // [b,h,d,q]
__device__ __align__(16) float g_ctxt[Bc * Pc * 256];
__device__ __align__(16) float g_oscr[2 * Bc * Pc * 256];  // [ks,b,p,256]
__device__ __align__(16) float2 g_mlscr[2 * Bc * 8 * Pc];  // [ks,b,g,p]

// ---------------------------------------------------------------------------
// GEMM: C = A[M,K] @ Bw[N,K]^T. EPI=1: per-head q/k/v fp16 epilogue.
// ---------------------------------------------------------------------------
template <int EPI>
__global__ __launch_bounds__(256) void gemm_nt(const float* __restrict__ A,
                                               const float* __restrict__ Bw,
                                               float* __restrict__ C,
                                               int M, int N, int K) {
    __shared__ __align__(16) float As[64][68];
    __shared__ __align__(16) float Bs[64][68];

    const int tid = threadIdx.x;
    const int tx = tid & 15, ty = tid >> 4;
    const int m0 = blockIdx.x << 6, n0 = blockIdx.y << 6;
    const int bn = tid & 63;
    const int bk = (tid >> 6) << 4;

    U64F2 acc[4][2];
#pragma unroll
    for (int i = 0; i < 4; i++) {
        acc[i][0].f = make_float2(0.f, 0.f);
        acc[i][1].f = make_float2(0.f, 0.f);
    }

    for (int kc = 0; kc < K; kc += 64) {
#pragma unroll
        for (int i = 0; i < 4; i++) {
            int v = tid + (i << 8);
            int r = v >> 4, k4 = v & 15;
            *(float4*)&As[r][k4 << 2] =
                *(const float4*)&A[(size_t)(m0 + r) * K + kc + (k4 << 2)];
        }
#pragma unroll
        for (int c4 = 0; c4 < 4; c4++) {
            float4 bv = *(const float4*)&Bw[(size_t)(n0 + bn) * K + kc + bk + (c4 << 2)];
            Bs[bk + (c4 << 2) + 0][bn] = bv.x;
            Bs[bk + (c4 << 2) + 1][bn] = bv.y;
            Bs[bk + (c4 << 2) + 2][bn] = bv.z;
            Bs[bk + (c4 << 2) + 3][bn] = bv.w;
        }
        __syncthreads();
#pragma unroll 8
        for (int kk = 0; kk < 64; kk++) {
            float4 b01 = *(const float4*)&Bs[kk][tx << 2];
            U64F2 b0, b1;
            b0.f = make_float2(b01.x, b01.y);
            b1.f = make_float2(b01.z, b01.w);
#pragma unroll
            for (int i = 0; i < 4; i++) {
                U64F2 a2 = pk2(As[(ty << 2) + i][kk]);
                acc[i][0] = f2fma(a2, b0, acc[i][0]);
                acc[i][1] = f2fma(a2, b1, acc[i][1]);
            }
        }
        __syncthreads();
    }

    if (EPI == 0) {
#pragma unroll
        for (int i = 0; i < 4; i++) {
            float4 vout;
            vout.x = acc[i][0].f.x; vout.y = acc[i][0].f.y;
            vout.z = acc[i][1].f.x; vout.w = acc[i][1].f.y;
            *(float4*)&C[(size_t)(m0 + (ty << 2) + i) * N + n0 + (tx << 2)] = vout;
        }
    } else {
#pragma unroll
        for (int i = 0; i < 4; i++) {
            float vals[4] = {acc[i][0].f.x, acc[i][0].f.y, acc[i][1].f.x, acc[i][1].f.y};
            int r = m0 + (ty << 2) + i;
            int bb = r >> 11, p = r & 2047;
#pragma unroll
            for (int j = 0; j < 4; j++) {
                int c = n0 + (tx << 2) + j;
                int sgrp = c >> 8;            // 0=q 1=k 2=v
                int h = (c >> 5) & 7, d = c & 31;
                float val = vals[j];
                size_t hp = ((size_t)(bb * 8 + h) * Pc + p) * 32 + d;
                if (sgrp == 0) {
                    g_qh[hp] = __float2half_rn(val * QSCALE);
                } else if (sgrp == 1) {
                    g_kh[hp] = __float2half_rn(val);
                } else {
                    g_vt[((size_t)(bb * 8 + h) * 32 + d) * Pc + p] = __float2half_rn(val);
                }
            }
        }
    }
}

// ---------------------------------------------------------------------------
// Fused talking-heads attention, MMA-everything fp16 design.
// CTA = (b, 32-row p-tile, key-split ks of 2). 256 thr, 8 warps.
//   QK  (warp=h): S_h[32p x 32q], K=32 -> S fp16 smem [p][q][h]
//   MIX (warp=p-set): T[q][g] = S^T W^T via m16n8k8, C-init = bias -> T fp32
//   PV  (warp=g): register softmax (R8 flow) + P@V fp16 single pass
// Bank bijections (la + 8lb pattern) verified per phase; see strides.
// ---------------------------------------------------------------------------
constexpr int K_OFF = 0;               // [h*32+q] rows 80B  -> 20480
constexpr int V_OFF = 20480;           // [g*32+d] rows 80B  -> 20480
constexpr int S_OFF = 40960;           // [p] stride 516B, [q] 16B, [h] 2B -> 16512
constexpr int T_OFF = 57472;           // [g] planes 5136B, [p] rows 160B -> 41088
constexpr int SM_ATTN = 98560;

__global__ __launch_bounds__(256, 2) void attn_mma(const float* __restrict__ bias,
                                                   const float* __restrict__ wtalk) {
    extern __shared__ char smem[];

    const int tid = threadIdx.x;
    const int w = tid >> 5, lane = tid & 31;
    const int la = lane >> 2, lb = lane & 3;
    const int b = blockIdx.x & 1;
    const int ks = (blockIdx.x >> 1) & 1;
    const int p0 = (blockIdx.x >> 2) << 5;

    const __half* kb = g_kh + (size_t)(b * 8) * Pc * 32;
    const __half* vb = g_vt + (size_t)(b * 8) * 32 * Pc;

    // Q A-fragments, head h=w, rows p0..p0+31, fp16
    uint32_t qf[2][2][4];
    {
        const __half* qb = g_qh + ((size_t)(b * 8 + w) * Pc + p0) * 32;
#pragma unroll
        for (int mt = 0; mt < 2; mt++)
#pragma unroll
            for (int k2 = 0; k2 < 2; k2++) {
                int d = 16 * k2 + 2 * lb;
                qf[mt][k2][0] = *(const uint32_t*)(qb + (16 * mt + la) * 32 + d);
                qf[mt][k2][1] = *(const uint32_t*)(qb + (16 * mt + la + 8) * 32 + d);
                qf[mt][k2][2] = *(const uint32_t*)(qb + (16 * mt + la) * 32 + d + 8);
                qf[mt][k2][3] = *(const uint32_t*)(qb + (16 * mt + la + 8) * 32 + d + 8);
            }
    }
    // W b-frag (constant): b0 = {W[la][2lb], W[la][2lb+1]}
    const uint32_t wfrag =
        packh(wtalk[la * 8 + 2 * lb], wtalk[la * 8 + 2 * lb + 1]);

    float o[2][4][4];
#pragma unroll
    for (int mt = 0; mt < 2; mt++)
#pragma unroll
        for (int nt = 0; nt < 4; nt++)
#pragma unroll
            for (int i = 0; i < 4; i++) o[mt][nt][i] = 0.f;
    float mr[2][2], lr[2][2];
#pragma unroll
    for (int mt = 0; mt < 2; mt++) {
        mr[mt][0] = -1e30f; mr[mt][1] = -1e30f;
        lr[mt][0] = 0.f;    lr[mt][1] = 0.f;
    }

    // bias base for the mix C-init: bias[g][p][q], g-stride Pc*Pc
    const float* bias_b = bias;

    for (int t = 0; t < 32; t++) {
        const int q0 = (2 * t + ks) * 32;

        // ---- mix C-init: bias at c-frag coords (issued early, gmem) ----
        float cm[8][4];
#pragma unroll
        for (int j = 0; j < 8; j++) {
            int pl = 4 * w + (j >> 1), qh = j & 1;
            const float* bp =
                bias_b + ((size_t)(2 * lb) * Pc + p0 + pl) * Pc + q0 + 16 * qh + la;
            cm[j][0] = bp[0];
            cm[j][1] = bp[(size_t)Pc * Pc];
            cm[j][2] = bp[8];
            cm[j][3] = bp[(size_t)Pc * Pc + 8];
        }

        __syncthreads();   // prev tile's PV done (T, V, S reusable)

        // ---- stage K [h][q][32d] fp16 rows 80B ----
        {
            const __half* src = kb + ((size_t)(tid >> 5) * Pc + q0 + (tid & 31)) * 32;
            char* dst = smem + K_OFF + tid * 80;
#pragma unroll
            for (int j = 0; j < 4; j++)
                *(uint4*)(dst + j * 16) = *(const uint4*)(src + j * 8);
        }
        // ---- stage V [g][d][q] fp16 rows 80B ----
        {
            const __half* src = vb + (size_t)tid * Pc + q0;
            char* dst = smem + V_OFF + tid * 80;
#pragma unroll
            for (int j = 0; j < 4; j++)
                *(uint4*)(dst + j * 16) = *(const uint4*)(src + j * 8);
        }
        __syncthreads();

        // ---- QK: S_h = Q_h @ K_h^T (warp = head), K=32, store fp16 ----
#pragma unroll
        for (int mt = 0; mt < 2; mt++) {
#pragma unroll
            for (int nt = 0; nt < 4; nt++) {
                float cc[4] = {0.f, 0.f, 0.f, 0.f};
#pragma unroll
                for (int k2 = 0; k2 < 2; k2++) {
                    const char* kp =
                        smem + K_OFF + (w * 32 + 8 * nt + la) * 80 + k2 * 32 + lb * 4;
                    uint32_t bb[2];
                    bb[0] = *(const uint32_t*)(kp);
                    bb[1] = *(const uint32_t*)(kp + 16);
                    mma16816h(cc, qf[mt][k2], bb);
                }
                // S[p][q][h]: p-stride 516B, q-stride 16B
                char* s0 = smem + S_OFF + (16 * mt + la) * 516 + (8 * nt + 2 * lb) * 16 + w * 2;
                *(__half*)(s0)             = __float2half_rn(cc[0]);
                *(__half*)(s0 + 16)        = __float2half_rn(cc[1]);
                *(__half*)(s0 + 8 * 516)   = __float2half_rn(cc[2]);
                *(__half*)(s0 + 8 * 516 + 16) = __float2half_rn(cc[3]);
            }
        }
        __syncthreads();

        // ---- MIX: T[q][g] = S[.][q][h] @ W^T + bias (warp w: p=4w..4w+3) ----
#pragma unroll
        for (int j = 0; j < 8; j++) {
            int pl = 4 * w + (j >> 1), qh = j & 1;
            const char* sp = smem + S_OFF + pl * 516 + (16 * qh + la) * 16 + lb * 4;
            uint32_t av[2];
            av[0] = *(const uint32_t*)(sp);
            av[1] = *(const uint32_t*)(sp + 128);   // q + 8
            mma16808h(cm[j], av, wfrag);
            // T[g][p][q] fp32: g-plane 5136B, p-row 160B
            char* t0 = smem + T_OFF + (2 * lb) * 5136 + pl * 160 + (16 * qh + la) * 4;
            *(float*)(t0)              = cm[j][0];
            *(float*)(t0 + 5136)       = cm[j][1];
            *(float*)(t0 + 32)         = cm[j][2];  // q + 8
            *(float*)(t0 + 5136 + 32)  = cm[j][3];
        }
        __syncthreads();

        // ---- PV: softmax in regs + P@V (warp = g) ----
        const char* tg = smem + T_OFF + w * 5136;
#pragma unroll
        for (int mt = 0; mt < 2; mt++) {
            const int rA = 16 * mt + la;
            float TA[8], TB[8];
#pragma unroll
            for (int kc = 0; kc < 2; kc++) {
                float2 u0 = *(const float2*)(tg + rA * 160 + (16 * kc + 2 * lb) * 4);
                float2 u1 = *(const float2*)(tg + rA * 160 + (16 * kc + 2 * lb + 8) * 4);
                float2 v0 = *(const float2*)(tg + (rA + 8) * 160 + (16 * kc + 2 * lb) * 4);
                float2 v1 = *(const float2*)(tg + (rA + 8) * 160 + (16 * kc + 2 * lb + 8) * 4);
                TA[4 * kc + 0] = u0.x; TA[4 * kc + 1] = u0.y;
                TA[4 * kc + 2] = u1.x; TA[4 * kc + 3] = u1.y;
                TB[4 * kc + 0] = v0.x; TB[4 * kc + 1] = v0.y;
                TB[4 * kc + 2] = v1.x; TB[4 * kc + 3] = v1.y;
            }
            float mxA = TA[0], mxB = TB[0];
#pragma unroll
            for (int i = 1; i < 8; i++) {
                mxA = fmaxf(mxA, TA[i]);
                mxB = fmaxf(mxB, TB[i]);
            }
            mxA = fmaxf(mxA, __shfl_xor_sync(0xffffffffu, mxA, 1));
            mxA = fmaxf(mxA, __shfl_xor_sync(0xffffffffu, mxA, 2));
            mxB = fmaxf(mxB, __shfl_xor_sync(0xffffffffu, mxB, 1));
            mxB = fmaxf(mxB, __shfl_xor_sync(0xffffffffu, mxB, 2));
            mxA = fmaxf(mxA, mr[mt][0]);
            mxB = fmaxf(mxB, mr[mt][1]);
            const float scA = __expf(mr[mt][0] - mxA);
            const float scB = __expf(mr[mt][1] - mxB);
            mr[mt][0] = mxA; mr[mt][1] = mxB;
            lr[mt][0] *= scA; lr[mt][1] *= scB;
#pragma unroll
            for (int nt = 0; nt < 4; nt++) {
                o[mt][nt][0] *= scA; o[mt][nt][1] *= scA;
                o[mt][nt][2] *= scB; o[mt][nt][3] *= scB;
            }
            float lsA = 0.f, lsB = 0.f;
#pragma unroll
            for (int i = 0; i < 8; i++) {
                TA[i] = __expf(TA[i] - mxA); lsA += TA[i];
                TB[i] = __expf(TB[i] - mxB); lsB += TB[i];
            }
            lr[mt][0] += lsA; lr[mt][1] += lsB;

#pragma unroll
            for (int kc = 0; kc < 2; kc++) {
                uint32_t phi[4];
                phi[0] = packh(TA[4 * kc + 0], TA[4 * kc + 1]);
                phi[1] = packh(TB[4 * kc + 0], TB[4 * kc + 1]);
                phi[2] = packh(TA[4 * kc + 2], TA[4 * kc + 3]);
                phi[3] = packh(TB[4 * kc + 2], TB[4 * kc + 3]);
#pragma unroll
                for (int nt = 0; nt < 4; nt++) {
                    const char* vp =
                        smem + V_OFF + (w * 32 + 8 * nt + la) * 80 + kc * 32 + lb * 4;
                    uint32_t bh[2];
                    bh[0] = *(const uint32_t*)(vp);
                    bh[1] = *(const uint32_t*)(vp + 16);
                    mma16816h(o[mt][nt], phi, bh);
                }
            }
        }
    }

    // ---- epilogue: write O partials + (m,l) per row to scratch ----
#pragma unroll
    for (int mt = 0; mt < 2; mt++) {
        float lA = lr[mt][0];
        lA += __shfl_xor_sync(0xffffffffu, lA, 1);
        lA += __shfl_xor_sync(0xffffffffu, lA, 2);
        float lB = lr[mt][1];
        lB += __shfl_xor_sync(0xffffffffu, lB, 1);
        lB += __shfl_xor_sync(0xffffffffu, lB, 2);
        const int rA = p0 + 16 * mt + la;
        float* obase = g_oscr + ((size_t)(ks * 2 + b) * Pc + rA) * 256 + w * 32 + 2 * lb;
#pragma unroll
        for (int nt = 0; nt < 4; nt++) {
            *(float2*)(obase + 8 * nt) = make_float2(o[mt][nt][0], o[mt][nt][1]);
            *(float2*)(obase + 8 * 256 + 8 * nt) = make_float2(o[mt][nt][2], o[mt][nt][3]);
        }
        if (lb == 0) {
            size_t mlb = ((size_t)(ks * 2 + b) * 8 + w) * Pc;
            g_mlscr[mlb + rA] = make_float2(mr[mt][0], lA);
            g_mlscr[mlb + rA + 8] = make_float2(mr[mt][1], lB);
        }
    }
}

// ---------------------------------------------------------------------------
// Key-split merge: ctxt = (e0*O0 + e1*O1) / (e0*l0 + e1*l1)
// ---------------------------------------------------------------------------
__global__ __launch_bounds__(256) void merge_k() {
    int idx = blockIdx.x * 256 + threadIdx.x;
    int c4 = idx & 63;
    int row = idx >> 6;                          // b*2048 + p
    int g = c4 >> 3;
    int b = row >> 11, p = row & 2047;
    float2 ml0 = g_mlscr[((size_t)(b * 8) + g) * Pc + p];
    float2 ml1 = g_mlscr[((size_t)((2 + b) * 8) + g) * Pc + p];
    float m = fmaxf(ml0.x, ml1.x);
    float e0 = __expf(ml0.x - m), e1 = __expf(ml1.x - m);
    float li = 1.0f / (e0 * ml0.y + e1 * ml1.y);
    e0 *= li; e1 *= li;
    const float4 a = *(const float4*)(g_oscr + (size_t)row * 256 + c4 * 4);
    const float4 c = *(const float4*)(g_oscr + (size_t)(Bc * Pc + row) * 256 + c4 * 4);
    float4 r;
    r.x = e0 * a.x + e1 * c.x;
    r.y = e0 * a.y + e1 * c.y;
    r.z = e0 * a.z + e1 * c.z;
    r.w = e0 * a.w + e1 * c.w;
    *(float4*)(g_ctxt + (size_t)row * 256 + c4 * 4) = r;
}

// ---------------------------------------------------------------------------
extern "C" void kernel_launch(void* const* d_in, const int* in_sizes, int n_in,
                              void* d_out, int out_size) {
    (void)in_sizes; (void)n_in; (void)out_size;
    const float* x     = (const float*)d_in[0];
    const float* bias  = (const float*)d_in[1];
    const float* wqkv  = (const float*)d_in[2];
    const float* wtalk = (const float*)d_in[3];
    const float* wproj = (const float*)d_in[4];
    float* out = (float*)d_out;

    cudaFuncSetAttribute(attn_mma, cudaFuncAttributeMaxDynamicSharedMemorySize,
                         SM_ATTN);

    void* ctxt_ptr = nullptr;
    cudaGetSymbolAddress(&ctxt_ptr, g_ctxt);

    // 1) QKV projection + per-head fp16 epilogue
    gemm_nt<1><<<dim3(64, 12), 256>>>(x, wqkv, nullptr, Bc * Pc, 3 * Hc * DFc, 128);

    // 2) fused attention (QK/mix/PV all on tensor pipe) -> partials
    attn_mma<<<Bc * 2 * (Pc / 32), 256, SM_ATTN>>>(bias, wtalk);

    // 3) key-split merge -> g_ctxt
    merge_k<<<1024, 256>>>();

    // 4) output projection
    gemm_nt<0><<<dim3(64, 2), 256>>>((const float*)ctxt_ptr, wproj, out,
                                     Bc * Pc, 128, Hc * DFc);
}

// round 14
// speedup vs baseline: 1.6290x; 1.1085x over previous
#include <cuda_runtime.h>
#include <cuda_fp16.h>
#include <cstdint>

#define DEV_INLINE __device__ __forceinline__

// ------------------------------- f32x2 helpers -----------------------------
struct U64F2 { union { unsigned long long u; float2 f; }; };
DEV_INLINE U64F2 f2fma(U64F2 a, U64F2 b, U64F2 c) {
    U64F2 d;
    asm("fma.rn.f32x2 %0, %1, %2, %3;" : "=l"(d.u) : "l"(a.u), "l"(b.u), "l"(c.u));
    return d;
}
DEV_INLINE U64F2 pk2(float v) {
    U64F2 d;
    asm("mov.b64 %0, {%1, %1};" : "=l"(d.u) : "f"(v));
    return d;
}

// ------------------------------- mma helpers (fp16) -----------------------
DEV_INLINE void mma16816h(float* c, const uint32_t* a, const uint32_t* b) {
    asm volatile(
        "mma.sync.aligned.m16n8k16.row.col.f32.f16.f16.f32 "
        "{%0,%1,%2,%3}, {%4,%5,%6,%7}, {%8,%9}, {%0,%1,%2,%3};"
        : "+f"(c[0]), "+f"(c[1]), "+f"(c[2]), "+f"(c[3])
        : "r"(a[0]), "r"(a[1]), "r"(a[2]), "r"(a[3]), "r"(b[0]), "r"(b[1]));
}
DEV_INLINE void mma16808h(float* c, const uint32_t* a, uint32_t b) {
    asm volatile(
        "mma.sync.aligned.m16n8k8.row.col.f32.f16.f16.f32 "
        "{%0,%1,%2,%3}, {%4,%5}, {%6}, {%0,%1,%2,%3};"
        : "+f"(c[0]), "+f"(c[1]), "+f"(c[2]), "+f"(c[3])
        : "r"(a[0]), "r"(a[1]), "r"(b));
}
DEV_INLINE uint32_t packh(float lo, float hi) {  // low half = lo
    uint32_t r;
    asm("cvt.rn.f16x2.f32 %0, %1, %2;" : "=r"(r) : "f"(hi), "f"(lo));
    return r;
}

// ------------------------------- problem constants ------------------------
constexpr int Bc = 2, Pc = 2048, Hc = 8, DFc = 32;
constexpr float QSCALE = 0.17677669529663687f;  // 1/sqrt(32)

__device__ __align__(16) __half g_xh[Bc * Pc * 128];      // x fp16 [4096,128]
__device__ __align__(16) __half g_wh[768 * 128];          // Wqkv fp16 [768,128]
__device__ __align__(16) __half g_qh[Bc * 8 * Pc * 32];   // [b,h,p,d] scaled
__device__ __align__(16) __half g_kh[Bc * 8 * Pc * 32];   // [b,h,q,d]
__device__ __align__(16) __half g_vt[Bc * 8 * 32 * Pc];   // [b,h,d,q]
__device__ __align__(16) float g_ctxt[Bc * Pc * 256];
__device__ __align__(16) float g_oscr[2 * Bc * Pc * 256];  // [ks,b,p,256]
__device__ __align__(16) float2 g_mlscr[2 * Bc * 8 * Pc];  // [ks,b,g,p]

// ---------------------------------------------------------------------------
// fp32 -> fp16 conversion (x, Wqkv)
// ---------------------------------------------------------------------------
__global__ __launch_bounds__(256) void cvt_f2h(const float* __restrict__ src,
                                               __half* __restrict__ dst, int n4) {
    int i = blockIdx.x * 256 + threadIdx.x;
    if (i < n4) {
        float4 v = ((const float4*)src)[i];
        __half2* d = (__half2*)dst + i * 2;
        d[0] = __floats2half2_rn(v.x, v.y);
        d[1] = __floats2half2_rn(v.z, v.w);
    }
}

// ---------------------------------------------------------------------------
// QKV projection on tensor pipe: qkv = x @ Wqkv^T, scatter epilogue.
// CTA tile 128m x 64n, K=128 staged fully. 8 warps: (wm 0..3) x (wn 0..1),
// warp tile 32x32. A/B smem rows 272B: word = 4*la+lb -> conflict-free.
// ---------------------------------------------------------------------------
DEV_INLINE void scatter_qkv(int r, int c, float val) {
    int bb = r >> 11, p = r & 2047;
    int sgrp = c >> 8, h = (c >> 5) & 7, d = c & 31;
    size_t hp = ((size_t)(bb * 8 + h) * Pc + p) * 32 + d;
    if (sgrp == 0)      g_qh[hp] = __float2half_rn(val * QSCALE);
    else if (sgrp == 1) g_kh[hp] = __float2half_rn(val);
    else g_vt[((size_t)(bb * 8 + h) * 32 + d) * Pc + p] = __float2half_rn(val);
}

__global__ __launch_bounds__(256, 2) void gemm_qkv_h() {
    __shared__ __align__(16) __half As[128][136];
    __shared__ __align__(16) __half Bs[64][136];

    const int tid = threadIdx.x;
    const int w = tid >> 5, lane = tid & 31;
    const int la = lane >> 2, lb = lane & 3;
    const int wm = w >> 1, wn = w & 1;
    const int m0 = blockIdx.x << 7, n0 = blockIdx.y << 6;

    // stage A (x tile 128x128 fp16) + B (W tile 64x128 fp16)
#pragma unroll
    for (int i = 0; i < 8; i++) {
        int idx = tid + (i << 8);
        int row = idx >> 4, c16 = idx & 15;
        *(uint4*)&As[row][c16 * 8] =
            *(const uint4*)(g_xh + (size_t)(m0 + row) * 128 + c16 * 8);
    }
#pragma unroll
    for (int i = 0; i < 4; i++) {
        int idx = tid + (i << 8);
        int row = idx >> 4, c16 = idx & 15;
        *(uint4*)&Bs[row][c16 * 8] =
            *(const uint4*)(g_wh + (size_t)(n0 + row) * 128 + c16 * 8);
    }
    __syncthreads();

    float c[2][4][4];
#pragma unroll
    for (int mt = 0; mt < 2; mt++)
#pragma unroll
        for (int nt = 0; nt < 4; nt++)
#pragma unroll
            for (int i = 0; i < 4; i++) c[mt][nt][i] = 0.f;

#pragma unroll
    for (int ks = 0; ks < 8; ks++) {
#pragma unroll
        for (int mt = 0; mt < 2; mt++) {
            uint32_t a[4];
            const __half* ab = &As[wm * 32 + 16 * mt + la][ks * 16 + 2 * lb];
            a[0] = *(const uint32_t*)(ab);
            a[1] = *(const uint32_t*)(ab + 8 * 136);
            a[2] = *(const uint32_t*)(ab + 8);
            a[3] = *(const uint32_t*)(ab + 8 * 136 + 8);
#pragma unroll
            for (int nt = 0; nt < 4; nt++) {
                uint32_t bb[2];
                const __half* bbp = &Bs[wn * 32 + 8 * nt + la][ks * 16 + 2 * lb];
                bb[0] = *(const uint32_t*)(bbp);
                bb[1] = *(const uint32_t*)(bbp + 8);
                mma16816h(c[mt][nt], a, bb);
            }
        }
    }

    // scatter epilogue (c-frag coords)
#pragma unroll
    for (int mt = 0; mt < 2; mt++)
#pragma unroll
        for (int nt = 0; nt < 4; nt++) {
            int r = m0 + wm * 32 + 16 * mt + la;
            int cc = n0 + wn * 32 + 8 * nt + 2 * lb;
            scatter_qkv(r,     cc,     c[mt][nt][0]);
            scatter_qkv(r,     cc + 1, c[mt][nt][1]);
            scatter_qkv(r + 8, cc,     c[mt][nt][2]);
            scatter_qkv(r + 8, cc + 1, c[mt][nt][3]);
        }
}

// ---------------------------------------------------------------------------
// GEMM (fp32 scalar): C = A[M,K] @ Bw[N,K]^T — used for output projection.
// ---------------------------------------------------------------------------
__global__ __launch_bounds__(256) void gemm_nt(const float* __restrict__ A,
                                               const float* __restrict__ Bw,
                                               float* __restrict__ C,
                                               int M, int N, int K) {
    __shared__ __align__(16) float As[64][68];
    __shared__ __align__(16) float Bs[64][68];

    const int tid = threadIdx.x;
    const int tx = tid & 15, ty = tid >> 4;
    const int m0 = blockIdx.x << 6, n0 = blockIdx.y << 6;
    const int bn = tid & 63;
    const int bk = (tid >> 6) << 4;

    U64F2 acc[4][2];
#pragma unroll
    for (int i = 0; i < 4; i++) {
        acc[i][0].f = make_float2(0.f, 0.f);
        acc[i][1].f = make_float2(0.f, 0.f);
    }

    for (int kc = 0; kc < K; kc += 64) {
#pragma unroll
        for (int i = 0; i < 4; i++) {
            int v = tid + (i << 8);
            int r = v >> 4, k4 = v & 15;
            *(float4*)&As[r][k4 << 2] =
                *(const float4*)&A[(size_t)(m0 + r) * K + kc + (k4 << 2)];
        }
#pragma unroll
        for (int c4 = 0; c4 < 4; c4++) {
            float4 bv = *(const float4*)&Bw[(size_t)(n0 + bn) * K + kc + bk + (c4 << 2)];
            Bs[bk + (c4 << 2) + 0][bn] = bv.x;
            Bs[bk + (c4 << 2) + 1][bn] = bv.y;
            Bs[bk + (c4 << 2) + 2][bn] = bv.z;
            Bs[bk + (c4 << 2) + 3][bn] = bv.w;
        }
        __syncthreads();
#pragma unroll 8
        for (int kk = 0; kk < 64; kk++) {
            float4 b01 = *(const float4*)&Bs[kk][tx << 2];
            U64F2 b0, b1;
            b0.f = make_float2(b01.x, b01.y);
            b1.f = make_float2(b01.z, b01.w);
#pragma unroll
            for (int i = 0; i < 4; i++) {
                U64F2 a2 = pk2(As[(ty << 2) + i][kk]);
                acc[i][0] = f2fma(a2, b0, acc[i][0]);
                acc[i][1] = f2fma(a2, b1, acc[i][1]);
            }
        }
        __syncthreads();
    }

#pragma unroll
    for (int i = 0; i < 4; i++) {
        float4 vout;
        vout.x = acc[i][0].f.x; vout.y = acc[i][0].f.y;
        vout.z = acc[i][1].f.x; vout.w = acc[i][1].f.y;
        *(float4*)&C[(size_t)(m0 + (ty << 2) + i) * N + n0 + (tx << 2)] = vout;
    }
}

// ---------------------------------------------------------------------------
// Fused talking-heads attention (verified R13 design, unchanged).
// ---------------------------------------------------------------------------
constexpr int K_OFF = 0;               // [h*32+q] rows 80B  -> 20480
constexpr int V_OFF = 20480;           // [g*32+d] rows 80B  -> 20480
constexpr int S_OFF = 40960;           // [p] stride 516B, [q] 16B, [h] 2B -> 16512
constexpr int T_OFF = 57472;           // [g] planes 5136B, [p] rows 160B -> 41088
constexpr int SM_ATTN = 98560;

__global__ __launch_bounds__(256, 2) void attn_mma(const float* __restrict__ bias,
                                                   const float* __restrict__ wtalk) {
    extern __shared__ char smem[];

    const int tid = threadIdx.x;
    const int w = tid >> 5, lane = tid & 31;
    const int la = lane >> 2, lb = lane & 3;
    const int b = blockIdx.x & 1;
    const int ks = (blockIdx.x >> 1) & 1;
    const int p0 = (blockIdx.x >> 2) << 5;

    const __half* kb = g_kh + (size_t)(b * 8) * Pc * 32;
    const __half* vb = g_vt + (size_t)(b * 8) * 32 * Pc;

    uint32_t qf[2][2][4];
    {
        const __half* qb = g_qh + ((size_t)(b * 8 + w) * Pc + p0) * 32;
#pragma unroll
        for (int mt = 0; mt < 2; mt++)
#pragma unroll
            for (int k2 = 0; k2 < 2; k2++) {
                int d = 16 * k2 + 2 * lb;
                qf[mt][k2][0] = *(const uint32_t*)(qb + (16 * mt + la) * 32 + d);
                qf[mt][k2][1] = *(const uint32_t*)(qb + (16 * mt + la + 8) * 32 + d);
                qf[mt][k2][2] = *(const uint32_t*)(qb + (16 * mt + la) * 32 + d + 8);
                qf[mt][k2][3] = *(const uint32_t*)(qb + (16 * mt + la + 8) * 32 + d + 8);
            }
    }
    const uint32_t wfrag =
        packh(wtalk[la * 8 + 2 * lb], wtalk[la * 8 + 2 * lb + 1]);

    float o[2][4][4];
#pragma unroll
    for (int mt = 0; mt < 2; mt++)
#pragma unroll
        for (int nt = 0; nt < 4; nt++)
#pragma unroll
            for (int i = 0; i < 4; i++) o[mt][nt][i] = 0.f;
    float mr[2][2], lr[2][2];
#pragma unroll
    for (int mt = 0; mt < 2; mt++) {
        mr[mt][0] = -1e30f; mr[mt][1] = -1e30f;
        lr[mt][0] = 0.f;    lr[mt][1] = 0.f;
    }

    const float* bias_b = bias;

    for (int t = 0; t < 32; t++) {
        const int q0 = (2 * t + ks) * 32;

        float cm[8][4];
#pragma unroll
        for (int j = 0; j < 8; j++) {
            int pl = 4 * w + (j >> 1), qh = j & 1;
            const float* bp =
                bias_b + ((size_t)(2 * lb) * Pc + p0 + pl) * Pc + q0 + 16 * qh + la;
            cm[j][0] = bp[0];
            cm[j][1] = bp[(size_t)Pc * Pc];
            cm[j][2] = bp[8];
            cm[j][3] = bp[(size_t)Pc * Pc + 8];
        }

        __syncthreads();

        {
            const __half* src = kb + ((size_t)(tid >> 5) * Pc + q0 + (tid & 31)) * 32;
            char* dst = smem + K_OFF + tid * 80;
#pragma unroll
            for (int j = 0; j < 4; j++)
                *(uint4*)(dst + j * 16) = *(const uint4*)(src + j * 8);
        }
        {
            const __half* src = vb + (size_t)tid * Pc + q0;
            char* dst = smem + V_OFF + tid * 80;
#pragma unroll
            for (int j = 0; j < 4; j++)
                *(uint4*)(dst + j * 16) = *(const uint4*)(src + j * 8);
        }
        __syncthreads();

#pragma unroll
        for (int mt = 0; mt < 2; mt++) {
#pragma unroll
            for (int nt = 0; nt < 4; nt++) {
                float cc[4] = {0.f, 0.f, 0.f, 0.f};
#pragma unroll
                for (int k2 = 0; k2 < 2; k2++) {
                    const char* kp =
                        smem + K_OFF + (w * 32 + 8 * nt + la) * 80 + k2 * 32 + lb * 4;
                    uint32_t bb[2];
                    bb[0] = *(const uint32_t*)(kp);
                    bb[1] = *(const uint32_t*)(kp + 16);
                    mma16816h(cc, qf[mt][k2], bb);
                }
                char* s0 = smem + S_OFF + (16 * mt + la) * 516 + (8 * nt + 2 * lb) * 16 + w * 2;
                *(__half*)(s0)                = __float2half_rn(cc[0]);
                *(__half*)(s0 + 16)           = __float2half_rn(cc[1]);
                *(__half*)(s0 + 8 * 516)      = __float2half_rn(cc[2]);
                *(__half*)(s0 + 8 * 516 + 16) = __float2half_rn(cc[3]);
            }
        }
        __syncthreads();

#pragma unroll
        for (int j = 0; j < 8; j++) {
            int pl = 4 * w + (j >> 1), qh = j & 1;
            const char* sp = smem + S_OFF + pl * 516 + (16 * qh + la) * 16 + lb * 4;
            uint32_t av[2];
            av[0] = *(const uint32_t*)(sp);
            av[1] = *(const uint32_t*)(sp + 128);
            mma16808h(cm[j], av, wfrag);
            char* t0 = smem + T_OFF + (2 * lb) * 5136 + pl * 160 + (16 * qh + la) * 4;
            *(float*)(t0)             = cm[j][0];
            *(float*)(t0 + 5136)      = cm[j][1];
            *(float*)(t0 + 32)        = cm[j][2];
            *(float*)(t0 + 5136 + 32) = cm[j][3];
        }
        __syncthreads();

        const char* tg = smem + T_OFF + w * 5136;
#pragma unroll
        for (int mt = 0; mt < 2; mt++) {
            const int rA = 16 * mt + la;
            float TA[8], TB[8];
#pragma unroll
            for (int kc = 0; kc < 2; kc++) {
                float2 u0 = *(const float2*)(tg + rA * 160 + (16 * kc + 2 * lb) * 4);
                float2 u1 = *(const float2*)(tg + rA * 160 + (16 * kc + 2 * lb + 8) * 4);
                float2 v0 = *(const float2*)(tg + (rA + 8) * 160 + (16 * kc + 2 * lb) * 4);
                float2 v1 = *(const float2*)(tg + (rA + 8) * 160 + (16 * kc + 2 * lb + 8) * 4);
                TA[4 * kc + 0] = u0.x; TA[4 * kc + 1] = u0.y;
                TA[4 * kc + 2] = u1.x; TA[4 * kc + 3] = u1.y;
                TB[4 * kc + 0] = v0.x; TB[4 * kc + 1] = v0.y;
                TB[4 * kc + 2] = v1.x; TB[4 * kc + 3] = v1.y;
            }
            float mxA = TA[0], mxB = TB[0];
#pragma unroll
            for (int i = 1; i < 8; i++) {
                mxA = fmaxf(mxA, TA[i]);
                mxB = fmaxf(mxB, TB[i]);
            }
            mxA = fmaxf(mxA, __shfl_xor_sync(0xffffffffu, mxA, 1));
            mxA = fmaxf(mxA, __shfl_xor_sync(0xffffffffu, mxA, 2));
            mxB = fmaxf(mxB, __shfl_xor_sync(0xffffffffu, mxB, 1));
            mxB = fmaxf(mxB, __shfl_xor_sync(0xffffffffu, mxB, 2));
            mxA = fmaxf(mxA, mr[mt][0]);
            mxB = fmaxf(mxB, mr[mt][1]);
            const float scA = __expf(mr[mt][0] - mxA);
            const float scB = __expf(mr[mt][1] - mxB);
            mr[mt][0] = mxA; mr[mt][1] = mxB;
            lr[mt][0] *= scA; lr[mt][1] *= scB;
#pragma unroll
            for (int nt = 0; nt < 4; nt++) {
                o[mt][nt][0] *= scA; o[mt][nt][1] *= scA;
                o[mt][nt][2] *= scB; o[mt][nt][3] *= scB;
            }
            float lsA = 0.f, lsB = 0.f;
#pragma unroll
            for (int i = 0; i < 8; i++) {
                TA[i] = __expf(TA[i] - mxA); lsA += TA[i];
                TB[i] = __expf(TB[i] - mxB); lsB += TB[i];
            }
            lr[mt][0] += lsA; lr[mt][1] += lsB;

#pragma unroll
            for (int kc = 0; kc < 2; kc++) {
                uint32_t phi[4];
                phi[0] = packh(TA[4 * kc + 0], TA[4 * kc + 1]);
                phi[1] = packh(TB[4 * kc + 0], TB[4 * kc + 1]);
                phi[2] = packh(TA[4 * kc + 2], TA[4 * kc + 3]);
                phi[3] = packh(TB[4 * kc + 2], TB[4 * kc + 3]);
#pragma unroll
                for (int nt = 0; nt < 4; nt++) {
                    const char* vp =
                        smem + V_OFF + (w * 32 + 8 * nt + la) * 80 + kc * 32 + lb * 4;
                    uint32_t bh[2];
                    bh[0] = *(const uint32_t*)(vp);
                    bh[1] = *(const uint32_t*)(vp + 16);
                    mma16816h(o[mt][nt], phi, bh);
                }
            }
        }
    }

#pragma unroll
    for (int mt = 0; mt < 2; mt++) {
        float lA = lr[mt][0];
        lA += __shfl_xor_sync(0xffffffffu, lA, 1);
        lA += __shfl_xor_sync(0xffffffffu, lA, 2);
        float lB = lr[mt][1];
        lB += __shfl_xor_sync(0xffffffffu, lB, 1);
        lB += __shfl_xor_sync(0xffffffffu, lB, 2);
        const int rA = p0 + 16 * mt + la;
        float* obase = g_oscr + ((size_t)(ks * 2 + b) * Pc + rA) * 256 + w * 32 + 2 * lb;
#pragma unroll
        for (int nt = 0; nt < 4; nt++) {
            *(float2*)(obase + 8 * nt) = make_float2(o[mt][nt][0], o[mt][nt][1]);
            *(float2*)(obase + 8 * 256 + 8 * nt) = make_float2(o[mt][nt][2], o[mt][nt][3]);
        }
        if (lb == 0) {
            size_t mlb = ((size_t)(ks * 2 + b) * 8 + w) * Pc;
            g_mlscr[mlb + rA] = make_float2(mr[mt][0], lA);
            g_mlscr[mlb + rA + 8] = make_float2(mr[mt][1], lB);
        }
    }
}

// ---------------------------------------------------------------------------
// Key-split merge: ctxt = (e0*O0 + e1*O1) / (e0*l0 + e1*l1)
// ---------------------------------------------------------------------------
__global__ __launch_bounds__(256) void merge_k() {
    int idx = blockIdx.x * 256 + threadIdx.x;
    int c4 = idx & 63;
    int row = idx >> 6;                          // b*2048 + p
    int g = c4 >> 3;
    int b = row >> 11, p = row & 2047;
    float2 ml0 = g_mlscr[((size_t)(b * 8) + g) * Pc + p];
    float2 ml1 = g_mlscr[((size_t)((2 + b) * 8) + g) * Pc + p];
    float m = fmaxf(ml0.x, ml1.x);
    float e0 = __expf(ml0.x - m), e1 = __expf(ml1.x - m);
    float li = 1.0f / (e0 * ml0.y + e1 * ml1.y);
    e0 *= li; e1 *= li;
    const float4 a = *(const float4*)(g_oscr + (size_t)row * 256 + c4 * 4);
    const float4 c = *(const float4*)(g_oscr + (size_t)(Bc * Pc + row) * 256 + c4 * 4);
    float4 r;
    r.x = e0 * a.x + e1 * c.x;
    r.y = e0 * a.y + e1 * c.y;
    r.z = e0 * a.z + e1 * c.z;
    r.w = e0 * a.w + e1 * c.w;
    *(float4*)(g_ctxt + (size_t)row * 256 + c4 * 4) = r;
}

// ---------------------------------------------------------------------------
extern "C" void kernel_launch(void* const* d_in, const int* in_sizes, int n_in,
                              void* d_out, int out_size) {
    (void)in_sizes; (void)n_in; (void)out_size;
    const float* x     = (const float*)d_in[0];
    const float* bias  = (const float*)d_in[1];
    const float* wqkv  = (const float*)d_in[2];
    const float* wtalk = (const float*)d_in[3];
    const float* wproj = (const float*)d_in[4];
    float* out = (float*)d_out;

    cudaFuncSetAttribute(attn_mma, cudaFuncAttributeMaxDynamicSharedMemorySize,
                         SM_ATTN);

    void* ctxt_ptr = nullptr;
    cudaGetSymbolAddress(&ctxt_ptr, g_ctxt);
    void* xh_ptr = nullptr;
    cudaGetSymbolAddress(&xh_ptr, g_xh);
    void* wh_ptr = nullptr;
    cudaGetSymbolAddress(&wh_ptr, g_wh);

    // 0) convert x, Wqkv to fp16
    cvt_f2h<<<(Bc * Pc * 128 / 4 + 255) / 256, 256>>>(x, (__half*)xh_ptr,
                                                      Bc * Pc * 128 / 4);
    cvt_f2h<<<(768 * 128 / 4 + 255) / 256, 256>>>(wqkv, (__half*)wh_ptr,
                                                  768 * 128 / 4);

    // 1) QKV projection (tensor pipe) + per-head fp16 scatter
    gemm_qkv_h<<<dim3(Bc * Pc / 128, 12), 256>>>();

    // 2) fused attention (QK/mix/PV all on tensor pipe) -> partials
    attn_mma<<<Bc * 2 * (Pc / 32), 256, SM_ATTN>>>(bias, wtalk);

    // 3) key-split merge -> g_ctxt
    merge_k<<<1024, 256>>>();

    // 4) output projection (fp32)
    gemm_nt<<<dim3(64, 2), 256>>>((const float*)ctxt_ptr, wproj, out,
                                  Bc * Pc, 128, Hc * DFc);
}

// round 15
// speedup vs baseline: 1.6629x; 1.0208x over previous
#include <cuda_runtime.h>
#include <cuda_fp16.h>
#include <cstdint>

#define DEV_INLINE __device__ __forceinline__

// ------------------------------- f32x2 helpers -----------------------------
struct U64F2 { union { unsigned long long u; float2 f; }; };
DEV_INLINE U64F2 f2fma(U64F2 a, U64F2 b, U64F2 c) {
    U64F2 d;
    asm("fma.rn.f32x2 %0, %1, %2, %3;" : "=l"(d.u) : "l"(a.u), "l"(b.u), "l"(c.u));
    return d;
}
DEV_INLINE U64F2 pk2(float v) {
    U64F2 d;
    asm("mov.b64 %0, {%1, %1};" : "=l"(d.u) : "f"(v));
    return d;
}

// ------------------------------- mma helpers (fp16) -----------------------
DEV_INLINE void mma16816h(float* c, const uint32_t* a, const uint32_t* b) {
    asm volatile(
        "mma.sync.aligned.m16n8k16.row.col.f32.f16.f16.f32 "
        "{%0,%1,%2,%3}, {%4,%5,%6,%7}, {%8,%9}, {%0,%1,%2,%3};"
        : "+f"(c[0]), "+f"(c[1]), "+f"(c[2]), "+f"(c[3])
        : "r"(a[0]), "r"(a[1]), "r"(a[2]), "r"(a[3]), "r"(b[0]), "r"(b[1]));
}
DEV_INLINE void mma16808h(float* c, const uint32_t* a, uint32_t b) {
    asm volatile(
        "mma.sync.aligned.m16n8k8.row.col.f32.f16.f16.f32 "
        "{%0,%1,%2,%3}, {%4,%5}, {%6}, {%0,%1,%2,%3};"
        : "+f"(c[0]), "+f"(c[1]), "+f"(c[2]), "+f"(c[3])
        : "r"(a[0]), "r"(a[1]), "r"(b));
}
DEV_INLINE uint32_t packh(float lo, float hi) {  // low half = lo
    uint32_t r;
    asm("cvt.rn.f16x2.f32 %0, %1, %2;" : "=r"(r) : "f"(hi), "f"(lo));
    return r;
}

// ------------------------------- problem constants ------------------------
constexpr int Bc = 2, Pc = 2048, Hc = 8, DFc = 32;
constexpr float QSCALE = 0.17677669529663687f;  // 1/sqrt(32)

__device__ __align__(16) __half g_xh[Bc * Pc * 128];      // x fp16 [4096,128]
__device__ __align__(16) __half g_wh[768 * 128];          // Wqkv fp16 [768,128]
__device__ __align__(16) __half g_qh[Bc * 8 * Pc * 32];   // [b,h,p,d] scaled
__device__ __align__(16) __half g_kh[Bc * 8 * Pc * 32];   // [b,h,q,d]
__device__ __align__(16) __half g_vt[Bc * 8 * 32 * Pc];   // [b,h,d,q]
__device__ __align__(16) float g_ctxt[Bc * Pc * 256];
__device__ __align__(16) float g_oscr[2 * Bc * Pc * 256];  // [ks,b,p,256]
__device__ __align__(16) float2 g_mlscr[2 * Bc * 8 * Pc];  // [ks,b,g,p]

// ---------------------------------------------------------------------------
// fp32 -> fp16 conversion (x, Wqkv)
// ---------------------------------------------------------------------------
__global__ __launch_bounds__(256) void cvt_f2h(const float* __restrict__ src,
                                               __half* __restrict__ dst, int n4) {
    int i = blockIdx.x * 256 + threadIdx.x;
    if (i < n4) {
        float4 v = ((const float4*)src)[i];
        __half2* d = (__half2*)dst + i * 2;
        d[0] = __floats2half2_rn(v.x, v.y);
        d[1] = __floats2half2_rn(v.z, v.w);
    }
}

// ---------------------------------------------------------------------------
// QKV projection on tensor pipe: qkv = x @ Wqkv^T, scatter epilogue.
// ---------------------------------------------------------------------------
DEV_INLINE void scatter_qkv(int r, int c, float val) {
    int bb = r >> 11, p = r & 2047;
    int sgrp = c >> 8, h = (c >> 5) & 7, d = c & 31;
    size_t hp = ((size_t)(bb * 8 + h) * Pc + p) * 32 + d;
    if (sgrp == 0)      g_qh[hp] = __float2half_rn(val * QSCALE);
    else if (sgrp == 1) g_kh[hp] = __float2half_rn(val);
    else g_vt[((size_t)(bb * 8 + h) * 32 + d) * Pc + p] = __float2half_rn(val);
}

__global__ __launch_bounds__(256, 2) void gemm_qkv_h() {
    __shared__ __align__(16) __half As[128][136];
    __shared__ __align__(16) __half Bs[64][136];

    const int tid = threadIdx.x;
    const int w = tid >> 5, lane = tid & 31;
    const int la = lane >> 2, lb = lane & 3;
    const int wm = w >> 1, wn = w & 1;
    const int m0 = blockIdx.x << 7, n0 = blockIdx.y << 6;

#pragma unroll
    for (int i = 0; i < 8; i++) {
        int idx = tid + (i << 8);
        int row = idx >> 4, c16 = idx & 15;
        *(uint4*)&As[row][c16 * 8] =
            *(const uint4*)(g_xh + (size_t)(m0 + row) * 128 + c16 * 8);
    }
#pragma unroll
    for (int i = 0; i < 4; i++) {
        int idx = tid + (i << 8);
        int row = idx >> 4, c16 = idx & 15;
        *(uint4*)&Bs[row][c16 * 8] =
            *(const uint4*)(g_wh + (size_t)(n0 + row) * 128 + c16 * 8);
    }
    __syncthreads();

    float c[2][4][4];
#pragma unroll
    for (int mt = 0; mt < 2; mt++)
#pragma unroll
        for (int nt = 0; nt < 4; nt++)
#pragma unroll
            for (int i = 0; i < 4; i++) c[mt][nt][i] = 0.f;

#pragma unroll
    for (int ks = 0; ks < 8; ks++) {
#pragma unroll
        for (int mt = 0; mt < 2; mt++) {
            uint32_t a[4];
            const __half* ab = &As[wm * 32 + 16 * mt + la][ks * 16 + 2 * lb];
            a[0] = *(const uint32_t*)(ab);
            a[1] = *(const uint32_t*)(ab + 8 * 136);
            a[2] = *(const uint32_t*)(ab + 8);
            a[3] = *(const uint32_t*)(ab + 8 * 136 + 8);
#pragma unroll
            for (int nt = 0; nt < 4; nt++) {
                uint32_t bb[2];
                const __half* bbp = &Bs[wn * 32 + 8 * nt + la][ks * 16 + 2 * lb];
                bb[0] = *(const uint32_t*)(bbp);
                bb[1] = *(const uint32_t*)(bbp + 8);
                mma16816h(c[mt][nt], a, bb);
            }
        }
    }

#pragma unroll
    for (int mt = 0; mt < 2; mt++)
#pragma unroll
        for (int nt = 0; nt < 4; nt++) {
            int r = m0 + wm * 32 + 16 * mt + la;
            int cc = n0 + wn * 32 + 8 * nt + 2 * lb;
            scatter_qkv(r,     cc,     c[mt][nt][0]);
            scatter_qkv(r,     cc + 1, c[mt][nt][1]);
            scatter_qkv(r + 8, cc,     c[mt][nt][2]);
            scatter_qkv(r + 8, cc + 1, c[mt][nt][3]);
        }
}

// ---------------------------------------------------------------------------
// GEMM (fp32 scalar): C = A[M,K] @ Bw[N,K]^T — output projection.
// ---------------------------------------------------------------------------
__global__ __launch_bounds__(256) void gemm_nt(const float* __restrict__ A,
                                               const float* __restrict__ Bw,
                                               float* __restrict__ C,
                                               int M, int N, int K) {
    __shared__ __align__(16) float As[64][68];
    __shared__ __align__(16) float Bs[64][68];

    const int tid = threadIdx.x;
    const int tx = tid & 15, ty = tid >> 4;
    const int m0 = blockIdx.x << 6, n0 = blockIdx.y << 6;
    const int bn = tid & 63;
    const int bk = (tid >> 6) << 4;

    U64F2 acc[4][2];
#pragma unroll
    for (int i = 0; i < 4; i++) {
        acc[i][0].f = make_float2(0.f, 0.f);
        acc[i][1].f = make_float2(0.f, 0.f);
    }

    for (int kc = 0; kc < K; kc += 64) {
#pragma unroll
        for (int i = 0; i < 4; i++) {
            int v = tid + (i << 8);
            int r = v >> 4, k4 = v & 15;
            *(float4*)&As[r][k4 << 2] =
                *(const float4*)&A[(size_t)(m0 + r) * K + kc + (k4 << 2)];
        }
#pragma unroll
        for (int c4 = 0; c4 < 4; c4++) {
            float4 bv = *(const float4*)&Bw[(size_t)(n0 + bn) * K + kc + bk + (c4 << 2)];
            Bs[bk + (c4 << 2) + 0][bn] = bv.x;
            Bs[bk + (c4 << 2) + 1][bn] = bv.y;
            Bs[bk + (c4 << 2) + 2][bn] = bv.z;
            Bs[bk + (c4 << 2) + 3][bn] = bv.w;
        }
        __syncthreads();
#pragma unroll 8
        for (int kk = 0; kk < 64; kk++) {
            float4 b01 = *(const float4*)&Bs[kk][tx << 2];
            U64F2 b0, b1;
            b0.f = make_float2(b01.x, b01.y);
            b1.f = make_float2(b01.z, b01.w);
#pragma unroll
            for (int i = 0; i < 4; i++) {
                U64F2 a2 = pk2(As[(ty << 2) + i][kk]);
                acc[i][0] = f2fma(a2, b0, acc[i][0]);
                acc[i][1] = f2fma(a2, b1, acc[i][1]);
            }
        }
        __syncthreads();
    }

#pragma unroll
    for (int i = 0; i < 4; i++) {
        float4 vout;
        vout.x = acc[i][0].f.x; vout.y = acc[i][0].f.y;
        vout.z = acc[i][1].f.x; vout.w = acc[i][1].f.y;
        *(float4*)&C[(size_t)(m0 + (ty << 2) + i) * N + n0 + (tx << 2)] = vout;
    }
}

// ---------------------------------------------------------------------------
// Fused talking-heads attention (R14 design; K/V fragment loads de-duplicated).
// ---------------------------------------------------------------------------
constexpr int K_OFF = 0;               // [h*32+q] rows 80B  -> 20480
constexpr int V_OFF = 20480;           // [g*32+d] rows 80B  -> 20480
constexpr int S_OFF = 40960;           // [p] stride 516B, [q] 16B, [h] 2B -> 16512
constexpr int T_OFF = 57472;           // [g] planes 5136B, [p] rows 160B -> 41088
constexpr int SM_ATTN = 98560;

__global__ __launch_bounds__(256, 2) void attn_mma(const float* __restrict__ bias,
                                                   const float* __restrict__ wtalk) {
    extern __shared__ char smem[];

    const int tid = threadIdx.x;
    const int w = tid >> 5, lane = tid & 31;
    const int la = lane >> 2, lb = lane & 3;
    const int b = blockIdx.x & 1;
    const int ks = (blockIdx.x >> 1) & 1;
    const int p0 = (blockIdx.x >> 2) << 5;

    const __half* kb = g_kh + (size_t)(b * 8) * Pc * 32;
    const __half* vb = g_vt + (size_t)(b * 8) * 32 * Pc;

    uint32_t qf[2][2][4];
    {
        const __half* qb = g_qh + ((size_t)(b * 8 + w) * Pc + p0) * 32;
#pragma unroll
        for (int mt = 0; mt < 2; mt++)
#pragma unroll
            for (int k2 = 0; k2 < 2; k2++) {
                int d = 16 * k2 + 2 * lb;
                qf[mt][k2][0] = *(const uint32_t*)(qb + (16 * mt + la) * 32 + d);
                qf[mt][k2][1] = *(const uint32_t*)(qb + (16 * mt + la + 8) * 32 + d);
                qf[mt][k2][2] = *(const uint32_t*)(qb + (16 * mt + la) * 32 + d + 8);
                qf[mt][k2][3] = *(const uint32_t*)(qb + (16 * mt + la + 8) * 32 + d + 8);
            }
    }
    const uint32_t wfrag =
        packh(wtalk[la * 8 + 2 * lb], wtalk[la * 8 + 2 * lb + 1]);

    float o[2][4][4];
#pragma unroll
    for (int mt = 0; mt < 2; mt++)
#pragma unroll
        for (int nt = 0; nt < 4; nt++)
#pragma unroll
            for (int i = 0; i < 4; i++) o[mt][nt][i] = 0.f;
    float mr[2][2], lr[2][2];
#pragma unroll
    for (int mt = 0; mt < 2; mt++) {
        mr[mt][0] = -1e30f; mr[mt][1] = -1e30f;
        lr[mt][0] = 0.f;    lr[mt][1] = 0.f;
    }

    const float* bias_b = bias;

    for (int t = 0; t < 32; t++) {
        const int q0 = (2 * t + ks) * 32;

        // ---- mix C-init: bias at c-frag coords ----
        float cm[8][4];
#pragma unroll
        for (int j = 0; j < 8; j++) {
            int pl = 4 * w + (j >> 1), qh = j & 1;
            const float* bp =
                bias_b + ((size_t)(2 * lb) * Pc + p0 + pl) * Pc + q0 + 16 * qh + la;
            cm[j][0] = bp[0];
            cm[j][1] = bp[(size_t)Pc * Pc];
            cm[j][2] = bp[8];
            cm[j][3] = bp[(size_t)Pc * Pc + 8];
        }

        __syncthreads();

        // ---- stage K / V ----
        {
            const __half* src = kb + ((size_t)(tid >> 5) * Pc + q0 + (tid & 31)) * 32;
            char* dst = smem + K_OFF + tid * 80;
#pragma unroll
            for (int j = 0; j < 4; j++)
                *(uint4*)(dst + j * 16) = *(const uint4*)(src + j * 8);
        }
        {
            const __half* src = vb + (size_t)tid * Pc + q0;
            char* dst = smem + V_OFF + tid * 80;
#pragma unroll
            for (int j = 0; j < 4; j++)
                *(uint4*)(dst + j * 16) = *(const uint4*)(src + j * 8);
        }
        __syncthreads();

        // ---- QK: S_h = Q_h @ K_h^T, K-frag loaded once per nt ----
#pragma unroll
        for (int nt = 0; nt < 4; nt++) {
            uint32_t bb[2][2];
#pragma unroll
            for (int k2 = 0; k2 < 2; k2++) {
                const char* kp =
                    smem + K_OFF + (w * 32 + 8 * nt + la) * 80 + k2 * 32 + lb * 4;
                bb[k2][0] = *(const uint32_t*)(kp);
                bb[k2][1] = *(const uint32_t*)(kp + 16);
            }
#pragma unroll
            for (int mt = 0; mt < 2; mt++) {
                float cc[4] = {0.f, 0.f, 0.f, 0.f};
                mma16816h(cc, qf[mt][0], bb[0]);
                mma16816h(cc, qf[mt][1], bb[1]);
                char* s0 = smem + S_OFF + (16 * mt + la) * 516 + (8 * nt + 2 * lb) * 16 + w * 2;
                *(__half*)(s0)                = __float2half_rn(cc[0]);
                *(__half*)(s0 + 16)           = __float2half_rn(cc[1]);
                *(__half*)(s0 + 8 * 516)      = __float2half_rn(cc[2]);
                *(__half*)(s0 + 8 * 516 + 16) = __float2half_rn(cc[3]);
            }
        }
        __syncthreads();

        // ---- MIX: T[q][g] = S @ W^T + bias ----
#pragma unroll
        for (int j = 0; j < 8; j++) {
            int pl = 4 * w + (j >> 1), qh = j & 1;
            const char* sp = smem + S_OFF + pl * 516 + (16 * qh + la) * 16 + lb * 4;
            uint32_t av[2];
            av[0] = *(const uint32_t*)(sp);
            av[1] = *(const uint32_t*)(sp + 128);
            mma16808h(cm[j], av, wfrag);
            char* t0 = smem + T_OFF + (2 * lb) * 5136 + pl * 160 + (16 * qh + la) * 4;
            *(float*)(t0)             = cm[j][0];
            *(float*)(t0 + 5136)      = cm[j][1];
            *(float*)(t0 + 32)        = cm[j][2];
            *(float*)(t0 + 5136 + 32) = cm[j][3];
        }
        __syncthreads();

        // ---- PV: softmax in regs -> phi; V-frag loaded once per (kc,nt) ----
        const char* tg = smem + T_OFF + w * 5136;
        uint32_t phi[2][2][4];
#pragma unroll
        for (int mt = 0; mt < 2; mt++) {
            const int rA = 16 * mt + la;
            float TA[8], TB[8];
#pragma unroll
            for (int kc = 0; kc < 2; kc++) {
                float2 u0 = *(const float2*)(tg + rA * 160 + (16 * kc + 2 * lb) * 4);
                float2 u1 = *(const float2*)(tg + rA * 160 + (16 * kc + 2 * lb + 8) * 4);
                float2 v0 = *(const float2*)(tg + (rA + 8) * 160 + (16 * kc + 2 * lb) * 4);
                float2 v1 = *(const float2*)(tg + (rA + 8) * 160 + (16 * kc + 2 * lb + 8) * 4);
                TA[4 * kc + 0] = u0.x; TA[4 * kc + 1] = u0.y;
                TA[4 * kc + 2] = u1.x; TA[4 * kc + 3] = u1.y;
                TB[4 * kc + 0] = v0.x; TB[4 * kc + 1] = v0.y;
                TB[4 * kc + 2] = v1.x; TB[4 * kc + 3] = v1.y;
            }
            float mxA = TA[0], mxB = TB[0];
#pragma unroll
            for (int i = 1; i < 8; i++) {
                mxA = fmaxf(mxA, TA[i]);
                mxB = fmaxf(mxB, TB[i]);
            }
            mxA = fmaxf(mxA, __shfl_xor_sync(0xffffffffu, mxA, 1));
            mxA = fmaxf(mxA, __shfl_xor_sync(0xffffffffu, mxA, 2));
            mxB = fmaxf(mxB, __shfl_xor_sync(0xffffffffu, mxB, 1));
            mxB = fmaxf(mxB, __shfl_xor_sync(0xffffffffu, mxB, 2));
            mxA = fmaxf(mxA, mr[mt][0]);
            mxB = fmaxf(mxB, mr[mt][1]);
            const float scA = __expf(mr[mt][0] - mxA);
            const float scB = __expf(mr[mt][1] - mxB);
            mr[mt][0] = mxA; mr[mt][1] = mxB;
            lr[mt][0] *= scA; lr[mt][1] *= scB;
#pragma unroll
            for (int nt = 0; nt < 4; nt++) {
                o[mt][nt][0] *= scA; o[mt][nt][1] *= scA;
                o[mt][nt][2] *= scB; o[mt][nt][3] *= scB;
            }
            float lsA = 0.f, lsB = 0.f;
#pragma unroll
            for (int i = 0; i < 8; i++) {
                TA[i] = __expf(TA[i] - mxA); lsA += TA[i];
                TB[i] = __expf(TB[i] - mxB); lsB += TB[i];
            }
            lr[mt][0] += lsA; lr[mt][1] += lsB;
#pragma unroll
            for (int kc = 0; kc < 2; kc++) {
                phi[mt][kc][0] = packh(TA[4 * kc + 0], TA[4 * kc + 1]);
                phi[mt][kc][1] = packh(TB[4 * kc + 0], TB[4 * kc + 1]);
                phi[mt][kc][2] = packh(TA[4 * kc + 2], TA[4 * kc + 3]);
                phi[mt][kc][3] = packh(TB[4 * kc + 2], TB[4 * kc + 3]);
            }
        }
#pragma unroll
        for (int kc = 0; kc < 2; kc++)
#pragma unroll
            for (int nt = 0; nt < 4; nt++) {
                const char* vp =
                    smem + V_OFF + (w * 32 + 8 * nt + la) * 80 + kc * 32 + lb * 4;
                uint32_t bh[2];
                bh[0] = *(const uint32_t*)(vp);
                bh[1] = *(const uint32_t*)(vp + 16);
                mma16816h(o[0][nt], phi[0][kc], bh);
                mma16816h(o[1][nt], phi[1][kc], bh);
            }
    }

    // ---- epilogue: write O partials + (m,l) per row to scratch ----
#pragma unroll
    for (int mt = 0; mt < 2; mt++) {
        float lA = lr[mt][0];
        lA += __shfl_xor_sync(0xffffffffu, lA, 1);
        lA += __shfl_xor_sync(0xffffffffu, lA, 2);
        float lB = lr[mt][1];
        lB += __shfl_xor_sync(0xffffffffu, lB, 1);
        lB += __shfl_xor_sync(0xffffffffu, lB, 2);
        const int rA = p0 + 16 * mt + la;
        float* obase = g_oscr + ((size_t)(ks * 2 + b) * Pc + rA) * 256 + w * 32 + 2 * lb;
#pragma unroll
        for (int nt = 0; nt < 4; nt++) {
            *(float2*)(obase + 8 * nt) = make_float2(o[mt][nt][0], o[mt][nt][1]);
            *(float2*)(obase + 8 * 256 + 8 * nt) = make_float2(o[mt][nt][2], o[mt][nt][3]);
        }
        if (lb == 0) {
            size_t mlb = ((size_t)(ks * 2 + b) * 8 + w) * Pc;
            g_mlscr[mlb + rA] = make_float2(mr[mt][0], lA);
            g_mlscr[mlb + rA + 8] = make_float2(mr[mt][1], lB);
        }
    }
}

// ---------------------------------------------------------------------------
// Key-split merge: ctxt = (e0*O0 + e1*O1) / (e0*l0 + e1*l1)
// ---------------------------------------------------------------------------
__global__ __launch_bounds__(256) void merge_k() {
    int idx = blockIdx.x * 256 + threadIdx.x;
    int c4 = idx & 63;
    int row = idx >> 6;                          // b*2048 + p
    int g = c4 >> 3;
    int b = row >> 11, p = row & 2047;
    float2 ml0 = g_mlscr[((size_t)(b * 8) + g) * Pc + p];
    float2 ml1 = g_mlscr[((size_t)((2 + b) * 8) + g) * Pc + p];
    float m = fmaxf(ml0.x, ml1.x);
    float e0 = __expf(ml0.x - m), e1 = __expf(ml1.x - m);
    float li = 1.0f / (e0 * ml0.y + e1 * ml1.y);
    e0 *= li; e1 *= li;
    const float4 a = *(const float4*)(g_oscr + (size_t)row * 256 + c4 * 4);
    const float4 c = *(const float4*)(g_oscr + (size_t)(Bc * Pc + row) * 256 + c4 * 4);
    float4 r;
    r.x = e0 * a.x + e1 * c.x;
    r.y = e0 * a.y + e1 * c.y;
    r.z = e0 * a.z + e1 * c.z;
    r.w = e0 * a.w + e1 * c.w;
    *(float4*)(g_ctxt + (size_t)row * 256 + c4 * 4) = r;
}

// ---------------------------------------------------------------------------
extern "C" void kernel_launch(void* const* d_in, const int* in_sizes, int n_in,
                              void* d_out, int out_size) {
    (void)in_sizes; (void)n_in; (void)out_size;
    const float* x     = (const float*)d_in[0];
    const float* bias  = (const float*)d_in[1];
    const float* wqkv  = (const float*)d_in[2];
    const float* wtalk = (const float*)d_in[3];
    const float* wproj = (const float*)d_in[4];
    float* out = (float*)d_out;

    cudaFuncSetAttribute(attn_mma, cudaFuncAttributeMaxDynamicSharedMemorySize,
                         SM_ATTN);

    void* ctxt_ptr = nullptr;
    cudaGetSymbolAddress(&ctxt_ptr, g_ctxt);
    void* xh_ptr = nullptr;
    cudaGetSymbolAddress(&xh_ptr, g_xh);
    void* wh_ptr = nullptr;
    cudaGetSymbolAddress(&wh_ptr, g_wh);

    // 0) convert x, Wqkv to fp16
    cvt_f2h<<<(Bc * Pc * 128 / 4 + 255) / 256, 256>>>(x, (__half*)xh_ptr,
                                                      Bc * Pc * 128 / 4);
    cvt_f2h<<<(768 * 128 / 4 + 255) / 256, 256>>>(wqkv, (__half*)wh_ptr,
                                                  768 * 128 / 4);

    // 1) QKV projection (tensor pipe) + per-head fp16 scatter
    gemm_qkv_h<<<dim3(Bc * Pc / 128, 12), 256>>>();

    // 2) fused attention (QK/mix/PV all on tensor pipe) -> partials
    attn_mma<<<Bc * 2 * (Pc / 32), 256, SM_ATTN>>>(bias, wtalk);

    // 3) key-split merge -> g_ctxt
    merge_k<<<1024, 256>>>();

    // 4) output projection (fp32)
    gemm_nt<<<dim3(64, 2), 256>>>((const float*)ctxt_ptr, wproj, out,
                                  Bc * Pc, 128, Hc * DFc);
}

// round 16
// speedup vs baseline: 1.7048x; 1.0252x over previous
#include <cuda_runtime.h>
#include <cuda_fp16.h>
#include <cstdint>

#define DEV_INLINE __device__ __forceinline__

// ------------------------------- helpers ----------------------------------
DEV_INLINE uint32_t smem_u32(const void* p) {
    uint32_t a;
    asm("{ .reg .u64 t; cvta.to.shared.u64 t, %1; cvt.u32.u64 %0, t; }"
        : "=r"(a) : "l"(p));
    return a;
}
DEV_INLINE void cpa16(uint32_t dst, const void* src) {
    asm volatile("cp.async.ca.shared.global [%0], [%1], 16;"
                 :: "r"(dst), "l"(src) : "memory");
}
DEV_INLINE void cpa_wait_all() {
    asm volatile("cp.async.commit_group;\n\tcp.async.wait_group 0;" ::: "memory");
}

DEV_INLINE void mma16816h(float* c, const uint32_t* a, const uint32_t* b) {
    asm volatile(
        "mma.sync.aligned.m16n8k16.row.col.f32.f16.f16.f32 "
        "{%0,%1,%2,%3}, {%4,%5,%6,%7}, {%8,%9}, {%0,%1,%2,%3};"
        : "+f"(c[0]), "+f"(c[1]), "+f"(c[2]), "+f"(c[3])
        : "r"(a[0]), "r"(a[1]), "r"(a[2]), "r"(a[3]), "r"(b[0]), "r"(b[1]));
}
DEV_INLINE void mma16808h(float* c, const uint32_t* a, uint32_t b) {
    asm volatile(
        "mma.sync.aligned.m16n8k8.row.col.f32.f16.f16.f32 "
        "{%0,%1,%2,%3}, {%4,%5}, {%6}, {%0,%1,%2,%3};"
        : "+f"(c[0]), "+f"(c[1]), "+f"(c[2]), "+f"(c[3])
        : "r"(a[0]), "r"(a[1]), "r"(b));
}
DEV_INLINE uint32_t packh(float lo, float hi) {  // low half = lo
    uint32_t r;
    asm("cvt.rn.f16x2.f32 %0, %1, %2;" : "=r"(r) : "f"(hi), "f"(lo));
    return r;
}

// ------------------------------- problem constants ------------------------
constexpr int Bc = 2, Pc = 2048, Hc = 8, DFc = 32;
constexpr float QSCALE = 0.17677669529663687f;  // 1/sqrt(32)

__device__ __align__(16) __half g_xh[Bc * Pc * 128];       // x fp16
__device__ __align__(16) __half g_wh[768 * 128];           // Wqkv fp16
__device__ __align__(16) __half g_wp[128 * 256];           // Wproj fp16
__device__ __align__(16) __half g_qh[Bc * 8 * Pc * 32];    // [b,h,p,d] scaled
__device__ __align__(16) __half g_kh[Bc * 8 * Pc * 32];    // [b,h,q,d]
__device__ __align__(16) __half g_vt[Bc * 8 * 32 * Pc];    // [b,h,d,q]
__device__ __align__(16) __half g_ctxt_h[Bc * Pc * 256];   // ctxt fp16
__device__ __align__(16) float g_oscr[2 * Bc * Pc * 256];  // [ks,b,p,256]
__device__ __align__(16) float2 g_mlscr[2 * Bc * 8 * Pc];  // [ks,b,g,p]

// ---------------------------------------------------------------------------
// fp32 -> fp16 conversion
// ---------------------------------------------------------------------------
__global__ __launch_bounds__(256) void cvt_f2h(const float* __restrict__ src,
                                               __half* __restrict__ dst, int n4) {
    int i = blockIdx.x * 256 + threadIdx.x;
    if (i < n4) {
        float4 v = ((const float4*)src)[i];
        __half2* d = (__half2*)dst + i * 2;
        d[0] = __floats2half2_rn(v.x, v.y);
        d[1] = __floats2half2_rn(v.z, v.w);
    }
}

// ---------------------------------------------------------------------------
// QKV projection on tensor pipe (verified R14): qkv = x @ Wqkv^T, scatter.
// ---------------------------------------------------------------------------
DEV_INLINE void scatter_qkv(int r, int c, float val) {
    int bb = r >> 11, p = r & 2047;
    int sgrp = c >> 8, h = (c >> 5) & 7, d = c & 31;
    size_t hp = ((size_t)(bb * 8 + h) * Pc + p) * 32 + d;
    if (sgrp == 0)      g_qh[hp] = __float2half_rn(val * QSCALE);
    else if (sgrp == 1) g_kh[hp] = __float2half_rn(val);
    else g_vt[((size_t)(bb * 8 + h) * 32 + d) * Pc + p] = __float2half_rn(val);
}

__global__ __launch_bounds__(256, 2) void gemm_qkv_h() {
    __shared__ __align__(16) __half As[128][136];
    __shared__ __align__(16) __half Bs[64][136];

    const int tid = threadIdx.x;
    const int w = tid >> 5, lane = tid & 31;
    const int la = lane >> 2, lb = lane & 3;
    const int wm = w >> 1, wn = w & 1;
    const int m0 = blockIdx.x << 7, n0 = blockIdx.y << 6;

#pragma unroll
    for (int i = 0; i < 8; i++) {
        int idx = tid + (i << 8);
        int row = idx >> 4, c16 = idx & 15;
        *(uint4*)&As[row][c16 * 8] =
            *(const uint4*)(g_xh + (size_t)(m0 + row) * 128 + c16 * 8);
    }
#pragma unroll
    for (int i = 0; i < 4; i++) {
        int idx = tid + (i << 8);
        int row = idx >> 4, c16 = idx & 15;
        *(uint4*)&Bs[row][c16 * 8] =
            *(const uint4*)(g_wh + (size_t)(n0 + row) * 128 + c16 * 8);
    }
    __syncthreads();

    float c[2][4][4];
#pragma unroll
    for (int mt = 0; mt < 2; mt++)
#pragma unroll
        for (int nt = 0; nt < 4; nt++)
#pragma unroll
            for (int i = 0; i < 4; i++) c[mt][nt][i] = 0.f;

#pragma unroll
    for (int ks = 0; ks < 8; ks++) {
#pragma unroll
        for (int mt = 0; mt < 2; mt++) {
            uint32_t a[4];
            const __half* ab = &As[wm * 32 + 16 * mt + la][ks * 16 + 2 * lb];
            a[0] = *(const uint32_t*)(ab);
            a[1] = *(const uint32_t*)(ab + 8 * 136);
            a[2] = *(const uint32_t*)(ab + 8);
            a[3] = *(const uint32_t*)(ab + 8 * 136 + 8);
#pragma unroll
            for (int nt = 0; nt < 4; nt++) {
                uint32_t bb[2];
                const __half* bbp = &Bs[wn * 32 + 8 * nt + la][ks * 16 + 2 * lb];
                bb[0] = *(const uint32_t*)(bbp);
                bb[1] = *(const uint32_t*)(bbp + 8);
                mma16816h(c[mt][nt], a, bb);
            }
        }
    }

#pragma unroll
    for (int mt = 0; mt < 2; mt++)
#pragma unroll
        for (int nt = 0; nt < 4; nt++) {
            int r = m0 + wm * 32 + 16 * mt + la;
            int cc = n0 + wn * 32 + 8 * nt + 2 * lb;
            scatter_qkv(r,     cc,     c[mt][nt][0]);
            scatter_qkv(r,     cc + 1, c[mt][nt][1]);
            scatter_qkv(r + 8, cc,     c[mt][nt][2]);
            scatter_qkv(r + 8, cc + 1, c[mt][nt][3]);
        }
}

// ---------------------------------------------------------------------------
// Output projection on tensor pipe: out = ctxt_h @ Wproj^T  (M=4096,N=128,K=256)
// ---------------------------------------------------------------------------
__global__ __launch_bounds__(256, 2) void gemm_proj(float* __restrict__ out) {
    __shared__ __align__(16) __half As[128][136];
    __shared__ __align__(16) __half Bs[64][136];

    const int tid = threadIdx.x;
    const int w = tid >> 5, lane = tid & 31;
    const int la = lane >> 2, lb = lane & 3;
    const int wm = w >> 1, wn = w & 1;
    const int m0 = blockIdx.x << 7, n0 = blockIdx.y << 6;

    float c[2][4][4];
#pragma unroll
    for (int mt = 0; mt < 2; mt++)
#pragma unroll
        for (int nt = 0; nt < 4; nt++)
#pragma unroll
            for (int i = 0; i < 4; i++) c[mt][nt][i] = 0.f;

    for (int kc = 0; kc < 256; kc += 128) {
        if (kc) __syncthreads();
#pragma unroll
        for (int i = 0; i < 8; i++) {
            int idx = tid + (i << 8);
            int row = idx >> 4, c16 = idx & 15;
            *(uint4*)&As[row][c16 * 8] =
                *(const uint4*)(g_ctxt_h + (size_t)(m0 + row) * 256 + kc + c16 * 8);
        }
#pragma unroll
        for (int i = 0; i < 4; i++) {
            int idx = tid + (i << 8);
            int row = idx >> 4, c16 = idx & 15;
            *(uint4*)&Bs[row][c16 * 8] =
                *(const uint4*)(g_wp + (size_t)(n0 + row) * 256 + kc + c16 * 8);
        }
        __syncthreads();

#pragma unroll
        for (int ks = 0; ks < 8; ks++) {
#pragma unroll
            for (int mt = 0; mt < 2; mt++) {
                uint32_t a[4];
                const __half* ab = &As[wm * 32 + 16 * mt + la][ks * 16 + 2 * lb];
                a[0] = *(const uint32_t*)(ab);
                a[1] = *(const uint32_t*)(ab + 8 * 136);
                a[2] = *(const uint32_t*)(ab + 8);
                a[3] = *(const uint32_t*)(ab + 8 * 136 + 8);
#pragma unroll
                for (int nt = 0; nt < 4; nt++) {
                    uint32_t bb[2];
                    const __half* bbp = &Bs[wn * 32 + 8 * nt + la][ks * 16 + 2 * lb];
                    bb[0] = *(const uint32_t*)(bbp);
                    bb[1] = *(const uint32_t*)(bbp + 8);
                    mma16816h(c[mt][nt], a, bb);
                }
            }
        }
    }

#pragma unroll
    for (int mt = 0; mt < 2; mt++)
#pragma unroll
        for (int nt = 0; nt < 4; nt++) {
            int r = m0 + wm * 32 + 16 * mt + la;
            int cc = n0 + wn * 32 + 8 * nt + 2 * lb;
            *(float2*)(out + (size_t)r * 128 + cc) =
                make_float2(c[mt][nt][0], c[mt][nt][1]);
            *(float2*)(out + (size_t)(r + 8) * 128 + cc) =
                make_float2(c[mt][nt][2], c[mt][nt][3]);
        }
}

// ---------------------------------------------------------------------------
// Fused talking-heads attention (R15 design; cp.async staging).
// ---------------------------------------------------------------------------
constexpr int K_OFF = 0;               // [h*32+q] rows 80B  -> 20480
constexpr int V_OFF = 20480;           // [g*32+d] rows 80B  -> 20480
constexpr int S_OFF = 40960;           // [p] stride 516B, [q] 16B, [h] 2B -> 16512
constexpr int T_OFF = 57472;           // [g] planes 5136B, [p] rows 160B -> 41088
constexpr int SM_ATTN = 98560;

__global__ __launch_bounds__(256, 2) void attn_mma(const float* __restrict__ bias,
                                                   const float* __restrict__ wtalk) {
    extern __shared__ char smem[];
    const uint32_t sb = smem_u32(smem);

    const int tid = threadIdx.x;
    const int w = tid >> 5, lane = tid & 31;
    const int la = lane >> 2, lb = lane & 3;
    const int b = blockIdx.x & 1;
    const int ks = (blockIdx.x >> 1) & 1;
    const int p0 = (blockIdx.x >> 2) << 5;

    const __half* kb = g_kh + (size_t)(b * 8) * Pc * 32;
    const __half* vb = g_vt + (size_t)(b * 8) * 32 * Pc;

    uint32_t qf[2][2][4];
    {
        const __half* qb = g_qh + ((size_t)(b * 8 + w) * Pc + p0) * 32;
#pragma unroll
        for (int mt = 0; mt < 2; mt++)
#pragma unroll
            for (int k2 = 0; k2 < 2; k2++) {
                int d = 16 * k2 + 2 * lb;
                qf[mt][k2][0] = *(const uint32_t*)(qb + (16 * mt + la) * 32 + d);
                qf[mt][k2][1] = *(const uint32_t*)(qb + (16 * mt + la + 8) * 32 + d);
                qf[mt][k2][2] = *(const uint32_t*)(qb + (16 * mt + la) * 32 + d + 8);
                qf[mt][k2][3] = *(const uint32_t*)(qb + (16 * mt + la + 8) * 32 + d + 8);
            }
    }
    const uint32_t wfrag =
        packh(wtalk[la * 8 + 2 * lb], wtalk[la * 8 + 2 * lb + 1]);

    float o[2][4][4];
#pragma unroll
    for (int mt = 0; mt < 2; mt++)
#pragma unroll
        for (int nt = 0; nt < 4; nt++)
#pragma unroll
            for (int i = 0; i < 4; i++) o[mt][nt][i] = 0.f;
    float mr[2][2], lr[2][2];
#pragma unroll
    for (int mt = 0; mt < 2; mt++) {
        mr[mt][0] = -1e30f; mr[mt][1] = -1e30f;
        lr[mt][0] = 0.f;    lr[mt][1] = 0.f;
    }

    for (int t = 0; t < 32; t++) {
        const int q0 = (2 * t + ks) * 32;

        // ---- mix C-init: bias at c-frag coords (sector-optimal) ----
        float cm[8][4];
#pragma unroll
        for (int j = 0; j < 8; j++) {
            int pl = 4 * w + (j >> 1), qh = j & 1;
            const float* bp =
                bias + ((size_t)(2 * lb) * Pc + p0 + pl) * Pc + q0 + 16 * qh + la;
            cm[j][0] = bp[0];
            cm[j][1] = bp[(size_t)Pc * Pc];
            cm[j][2] = bp[8];
            cm[j][3] = bp[(size_t)Pc * Pc + 8];
        }

        __syncthreads();

        // ---- stage K / V via cp.async (single LSU pass) ----
        {
            const __half* srcK = kb + ((size_t)(tid >> 5) * Pc + q0 + (tid & 31)) * 32;
            const __half* srcV = vb + (size_t)tid * Pc + q0;
            uint32_t dstK = sb + K_OFF + tid * 80;
            uint32_t dstV = sb + V_OFF + tid * 80;
#pragma unroll
            for (int j = 0; j < 4; j++) {
                cpa16(dstK + j * 16, srcK + j * 8);
                cpa16(dstV + j * 16, srcV + j * 8);
            }
        }
        cpa_wait_all();
        __syncthreads();

        // ---- QK: S_h = Q_h @ K_h^T (warp = head) ----
#pragma unroll
        for (int nt = 0; nt < 4; nt++) {
            uint32_t bb[2][2];
#pragma unroll
            for (int k2 = 0; k2 < 2; k2++) {
                const char* kp =
                    smem + K_OFF + (w * 32 + 8 * nt + la) * 80 + k2 * 32 + lb * 4;
                bb[k2][0] = *(const uint32_t*)(kp);
                bb[k2][1] = *(const uint32_t*)(kp + 16);
            }
#pragma unroll
            for (int mt = 0; mt < 2; mt++) {
                float cc[4] = {0.f, 0.f, 0.f, 0.f};
                mma16816h(cc, qf[mt][0], bb[0]);
                mma16816h(cc, qf[mt][1], bb[1]);
                char* s0 = smem + S_OFF + (16 * mt + la) * 516 + (8 * nt + 2 * lb) * 16 + w * 2;
                *(__half*)(s0)                = __float2half_rn(cc[0]);
                *(__half*)(s0 + 16)           = __float2half_rn(cc[1]);
                *(__half*)(s0 + 8 * 516)      = __float2half_rn(cc[2]);
                *(__half*)(s0 + 8 * 516 + 16) = __float2half_rn(cc[3]);
            }
        }
        __syncthreads();

        // ---- MIX: T[q][g] = S @ W^T + bias ----
#pragma unroll
        for (int j = 0; j < 8; j++) {
            int pl = 4 * w + (j >> 1), qh = j & 1;
            const char* sp = smem + S_OFF + pl * 516 + (16 * qh + la) * 16 + lb * 4;
            uint32_t av[2];
            av[0] = *(const uint32_t*)(sp);
            av[1] = *(const uint32_t*)(sp + 128);
            mma16808h(cm[j], av, wfrag);
            char* t0 = smem + T_OFF + (2 * lb) * 5136 + pl * 160 + (16 * qh + la) * 4;
            *(float*)(t0)             = cm[j][0];
            *(float*)(t0 + 5136)      = cm[j][1];
            *(float*)(t0 + 32)        = cm[j][2];
            *(float*)(t0 + 5136 + 32) = cm[j][3];
        }
        __syncthreads();

        // ---- PV: softmax in regs -> phi; single-pass fp16 P@V ----
        const char* tg = smem + T_OFF + w * 5136;
        uint32_t phi[2][2][4];
#pragma unroll
        for (int mt = 0; mt < 2; mt++) {
            const int rA = 16 * mt + la;
            float TA[8], TB[8];
#pragma unroll
            for (int kc = 0; kc < 2; kc++) {
                float2 u0 = *(const float2*)(tg + rA * 160 + (16 * kc + 2 * lb) * 4);
                float2 u1 = *(const float2*)(tg + rA * 160 + (16 * kc + 2 * lb + 8) * 4);
                float2 v0 = *(const float2*)(tg + (rA + 8) * 160 + (16 * kc + 2 * lb) * 4);
                float2 v1 = *(const float2*)(tg + (rA + 8) * 160 + (16 * kc + 2 * lb + 8) * 4);
                TA[4 * kc + 0] = u0.x; TA[4 * kc + 1] = u0.y;
                TA[4 * kc + 2] = u1.x; TA[4 * kc + 3] = u1.y;
                TB[4 * kc + 0] = v0.x; TB[4 * kc + 1] = v0.y;
                TB[4 * kc + 2] = v1.x; TB[4 * kc + 3] = v1.y;
            }
            float mxA = TA[0], mxB = TB[0];
#pragma unroll
            for (int i = 1; i < 8; i++) {
                mxA = fmaxf(mxA, TA[i]);
                mxB = fmaxf(mxB, TB[i]);
            }
            mxA = fmaxf(mxA, __shfl_xor_sync(0xffffffffu, mxA, 1));
            mxA = fmaxf(mxA, __shfl_xor_sync(0xffffffffu, mxA, 2));
            mxB = fmaxf(mxB, __shfl_xor_sync(0xffffffffu, mxB, 1));
            mxB = fmaxf(mxB, __shfl_xor_sync(0xffffffffu, mxB, 2));
            mxA = fmaxf(mxA, mr[mt][0]);
            mxB = fmaxf(mxB, mr[mt][1]);
            const float scA = __expf(mr[mt][0] - mxA);
            const float scB = __expf(mr[mt][1] - mxB);
            mr[mt][0] = mxA; mr[mt][1] = mxB;
            lr[mt][0] *= scA; lr[mt][1] *= scB;
#pragma unroll
            for (int nt = 0; nt < 4; nt++) {
                o[mt][nt][0] *= scA; o[mt][nt][1] *= scA;
                o[mt][nt][2] *= scB; o[mt][nt][3] *= scB;
            }
            float lsA = 0.f, lsB = 0.f;
#pragma unroll
            for (int i = 0; i < 8; i++) {
                TA[i] = __expf(TA[i] - mxA); lsA += TA[i];
                TB[i] = __expf(TB[i] - mxB); lsB += TB[i];
            }
            lr[mt][0] += lsA; lr[mt][1] += lsB;
#pragma unroll
            for (int kc = 0; kc < 2; kc++) {
                phi[mt][kc][0] = packh(TA[4 * kc + 0], TA[4 * kc + 1]);
                phi[mt][kc][1] = packh(TB[4 * kc + 0], TB[4 * kc + 1]);
                phi[mt][kc][2] = packh(TA[4 * kc + 2], TA[4 * kc + 3]);
                phi[mt][kc][3] = packh(TB[4 * kc + 2], TB[4 * kc + 3]);
            }
        }
#pragma unroll
        for (int kc = 0; kc < 2; kc++)
#pragma unroll
            for (int nt = 0; nt < 4; nt++) {
                const char* vp =
                    smem + V_OFF + (w * 32 + 8 * nt + la) * 80 + kc * 32 + lb * 4;
                uint32_t bh[2];
                bh[0] = *(const uint32_t*)(vp);
                bh[1] = *(const uint32_t*)(vp + 16);
                mma16816h(o[0][nt], phi[0][kc], bh);
                mma16816h(o[1][nt], phi[1][kc], bh);
            }
    }

    // ---- epilogue: write O partials + (m,l) to scratch ----
#pragma unroll
    for (int mt = 0; mt < 2; mt++) {
        float lA = lr[mt][0];
        lA += __shfl_xor_sync(0xffffffffu, lA, 1);
        lA += __shfl_xor_sync(0xffffffffu, lA, 2);
        float lB = lr[mt][1];
        lB += __shfl_xor_sync(0xffffffffu, lB, 1);
        lB += __shfl_xor_sync(0xffffffffu, lB, 2);
        const int rA = p0 + 16 * mt + la;
        float* obase = g_oscr + ((size_t)(ks * 2 + b) * Pc + rA) * 256 + w * 32 + 2 * lb;
#pragma unroll
        for (int nt = 0; nt < 4; nt++) {
            *(float2*)(obase + 8 * nt) = make_float2(o[mt][nt][0], o[mt][nt][1]);
            *(float2*)(obase + 8 * 256 + 8 * nt) = make_float2(o[mt][nt][2], o[mt][nt][3]);
        }
        if (lb == 0) {
            size_t mlb = ((size_t)(ks * 2 + b) * 8 + w) * Pc;
            g_mlscr[mlb + rA] = make_float2(mr[mt][0], lA);
            g_mlscr[mlb + rA + 8] = make_float2(mr[mt][1], lB);
        }
    }
}

// ---------------------------------------------------------------------------
// Key-split merge -> ctxt (fp16)
// ---------------------------------------------------------------------------
__global__ __launch_bounds__(256) void merge_k() {
    int idx = blockIdx.x * 256 + threadIdx.x;
    int c4 = idx & 63;
    int row = idx >> 6;                          // b*2048 + p
    int g = c4 >> 3;
    int b = row >> 11, p = row & 2047;
    float2 ml0 = g_mlscr[((size_t)(b * 8) + g) * Pc + p];
    float2 ml1 = g_mlscr[((size_t)((2 + b) * 8) + g) * Pc + p];
    float m = fmaxf(ml0.x, ml1.x);
    float e0 = __expf(ml0.x - m), e1 = __expf(ml1.x - m);
    float li = 1.0f / (e0 * ml0.y + e1 * ml1.y);
    e0 *= li; e1 *= li;
    const float4 a = *(const float4*)(g_oscr + (size_t)row * 256 + c4 * 4);
    const float4 c = *(const float4*)(g_oscr + (size_t)(Bc * Pc + row) * 256 + c4 * 4);
    __half2* dst = (__half2*)(g_ctxt_h + (size_t)row * 256 + c4 * 4);
    dst[0] = __floats2half2_rn(e0 * a.x + e1 * c.x, e0 * a.y + e1 * c.y);
    dst[1] = __floats2half2_rn(e0 * a.z + e1 * c.z, e0 * a.w + e1 * c.w);
}

// ---------------------------------------------------------------------------
extern "C" void kernel_launch(void* const* d_in, const int* in_sizes, int n_in,
                              void* d_out, int out_size) {
    (void)in_sizes; (void)n_in; (void)out_size;
    const float* x     = (const float*)d_in[0];
    const float* bias  = (const float*)d_in[1];
    const float* wqkv  = (const float*)d_in[2];
    const float* wtalk = (const float*)d_in[3];
    const float* wproj = (const float*)d_in[4];
    float* out = (float*)d_out;

    cudaFuncSetAttribute(attn_mma, cudaFuncAttributeMaxDynamicSharedMemorySize,
                         SM_ATTN);

    void* xh_ptr = nullptr;  cudaGetSymbolAddress(&xh_ptr, g_xh);
    void* wh_ptr = nullptr;  cudaGetSymbolAddress(&wh_ptr, g_wh);
    void* wp_ptr = nullptr;  cudaGetSymbolAddress(&wp_ptr, g_wp);

    // 0) convert x, Wqkv, Wproj to fp16
    cvt_f2h<<<(Bc * Pc * 128 / 4 + 255) / 256, 256>>>(x, (__half*)xh_ptr,
                                                      Bc * Pc * 128 / 4);
    cvt_f2h<<<(768 * 128 / 4 + 255) / 256, 256>>>(wqkv, (__half*)wh_ptr,
                                                  768 * 128 / 4);
    cvt_f2h<<<(128 * 256 / 4 + 255) / 256, 256>>>(wproj, (__half*)wp_ptr,
                                                  128 * 256 / 4);

    // 1) QKV projection (tensor pipe) + per-head fp16 scatter
    gemm_qkv_h<<<dim3(Bc * Pc / 128, 12), 256>>>();

    // 2) fused attention (QK/mix/PV all on tensor pipe) -> partials
    attn_mma<<<Bc * 2 * (Pc / 32), 256, SM_ATTN>>>(bias, wtalk);

    // 3) key-split merge -> ctxt fp16
    merge_k<<<1024, 256>>>();

    // 4) output projection (tensor pipe)
    gemm_proj<<<dim3(Bc * Pc / 128, 2), 256>>>(out);
}